// round 1
// baseline (speedup 1.0000x reference)
#include <cuda_runtime.h>
#include <cuda_bf16.h>
#include <math_constants.h>

// Problem constants
#define B_   64
#define N_   577
#define D_   768
#define H_   12
#define HD_  64
#define KK_  57            // int(576*0.1)
#define SELN 58            // 1 + KK_
#define M_ALL (B_ * N_)    // 36928
#define M_SEL (B_ * SELN)  // 3712

// ---------------- scratch (device globals; no allocations allowed) ------------
__device__ int   g_sel[B_ * SELN];
__device__ float g_xsel[M_SEL * D_];
__device__ float g_qsel[M_SEL * D_];
__device__ float g_kall[(size_t)M_ALL * D_];
__device__ float g_vall[(size_t)M_ALL * D_];
__device__ float g_lout[M_SEL * D_];
__device__ float g_y[(size_t)M_ALL * D_];

// ---------------- top-k (iterative argmax, one block per batch) ---------------
__global__ void topk_kernel(const float* __restrict__ acc, int* __restrict__ sel) {
    int b = blockIdx.x;
    __shared__ float vals[N_ - 1];
    __shared__ float rv[256];
    __shared__ int   ri[256];
    int t = threadIdx.x;
    const float* src = acc + (size_t)b * N_ * N_ + 1; // [b,0,1:]
    for (int i = t; i < N_ - 1; i += 256) vals[i] = src[i];
    if (t == 0) sel[b * SELN] = 0;
    __syncthreads();
    for (int it = 0; it < KK_; it++) {
        float best = -CUDART_INF_F; int bi = 0;
        for (int i = t; i < N_ - 1; i += 256) {
            float v = vals[i];
            if (v > best) { best = v; bi = i; }
        }
        rv[t] = best; ri[t] = bi;
        __syncthreads();
        for (int s = 128; s > 0; s >>= 1) {
            if (t < s && rv[t + s] > rv[t]) { rv[t] = rv[t + s]; ri[t] = ri[t + s]; }
            __syncthreads();
        }
        if (t == 0) { sel[b * SELN + 1 + it] = ri[0] + 1; vals[ri[0]] = -CUDART_INF_F; }
        __syncthreads();
    }
}

// ---------------- gather selected x rows --------------------------------------
__global__ void gather_rows_kernel(const float* __restrict__ x,
                                   const int* __restrict__ sel,
                                   float* __restrict__ dst) {
    int m = blockIdx.x;               // 0..M_SEL-1
    int b = m / SELN, j = m % SELN;
    int tok = sel[b * SELN + j];
    const float4* s = (const float4*)(x + ((size_t)b * N_ + tok) * D_);
    float4* d = (float4*)(dst + (size_t)m * D_);
    for (int i = threadIdx.x; i < D_ / 4; i += blockDim.x) d[i] = s[i];
}

// ---------------- copy x -> y (grid-stride float4) ----------------------------
__global__ void copy_kernel(const float* __restrict__ x, float* __restrict__ y, size_t n4) {
    size_t i = (size_t)blockIdx.x * blockDim.x + threadIdx.x;
    size_t stride = (size_t)gridDim.x * blockDim.x;
    const float4* s = (const float4*)x;
    float4* d = (float4*)y;
    for (; i < n4; i += stride) d[i] = s[i];
}

// ---------------- scatter local_out rows into y -------------------------------
__global__ void scatter_rows_kernel(const float* __restrict__ lout,
                                    const int* __restrict__ sel,
                                    float* __restrict__ y) {
    int m = blockIdx.x;
    int b = m / SELN, j = m % SELN;
    int tok = sel[b * SELN + j];
    const float4* s = (const float4*)(lout + (size_t)m * D_);
    float4* d = (float4*)(y + ((size_t)b * N_ + tok) * D_);
    for (int i = threadIdx.x; i < D_ / 4; i += blockDim.x) d[i] = s[i];
}

// ---------------- SGEMM: C[m,n] = sum_k A[m,k]*W[n,k] (+bias[n]) --------------
#define GBM 128
#define GBN 128
#define GBK 16
__global__ __launch_bounds__(256) void gemm_tn_kernel(
    const float* __restrict__ A, const float* __restrict__ W,
    const float* __restrict__ bias, float* __restrict__ C,
    int M, int N, int K)
{
    __shared__ __align__(16) float As[GBK][GBM + 4];
    __shared__ __align__(16) float Ws[GBK][GBN + 4];
    int tid = threadIdx.x;
    int tx = tid & 15, ty = tid >> 4;
    int bm = blockIdx.y * GBM, bn = blockIdx.x * GBN;

    float acc[8][8];
#pragma unroll
    for (int i = 0; i < 8; i++)
#pragma unroll
        for (int j = 0; j < 8; j++) acc[i][j] = 0.f;

    int lrow = tid >> 2;        // 0..63
    int lk   = (tid & 3) * 4;   // 0,4,8,12

    for (int k0 = 0; k0 < K; k0 += GBK) {
#pragma unroll
        for (int h = 0; h < 2; h++) {
            int r = lrow + h * 64;
            int gm = bm + r;
            float4 av = make_float4(0.f, 0.f, 0.f, 0.f);
            if (gm < M) av = *(const float4*)(A + (size_t)gm * K + k0 + lk);
            As[lk + 0][r] = av.x; As[lk + 1][r] = av.y;
            As[lk + 2][r] = av.z; As[lk + 3][r] = av.w;
            float4 wv = *(const float4*)(W + (size_t)(bn + r) * K + k0 + lk);
            Ws[lk + 0][r] = wv.x; Ws[lk + 1][r] = wv.y;
            Ws[lk + 2][r] = wv.z; Ws[lk + 3][r] = wv.w;
        }
        __syncthreads();
#pragma unroll
        for (int kk = 0; kk < GBK; kk++) {
            float a[8], w[8];
            *(float4*)&a[0] = *(const float4*)&As[kk][ty * 8];
            *(float4*)&a[4] = *(const float4*)&As[kk][ty * 8 + 4];
            *(float4*)&w[0] = *(const float4*)&Ws[kk][tx * 8];
            *(float4*)&w[4] = *(const float4*)&Ws[kk][tx * 8 + 4];
#pragma unroll
            for (int i = 0; i < 8; i++)
#pragma unroll
                for (int j = 0; j < 8; j++)
                    acc[i][j] = fmaf(a[i], w[j], acc[i][j]);
        }
        __syncthreads();
    }

#pragma unroll
    for (int i = 0; i < 8; i++) {
        int gm = bm + ty * 8 + i;
        if (gm < M) {
#pragma unroll
            for (int j = 0; j < 8; j += 4) {
                int gn = bn + tx * 8 + j;
                float4 o;
                o.x = acc[i][j + 0]; o.y = acc[i][j + 1];
                o.z = acc[i][j + 2]; o.w = acc[i][j + 3];
                if (bias) {
                    o.x += bias[gn + 0]; o.y += bias[gn + 1];
                    o.z += bias[gn + 2]; o.w += bias[gn + 3];
                }
                *(float4*)(C + (size_t)gm * N + gn) = o;
            }
        }
    }
}

// ---------------- attention: one block per (b, h, query j) --------------------
__global__ __launch_bounds__(128) void attn_kernel(
    const float* __restrict__ qsel, const float* __restrict__ kall,
    const float* __restrict__ vall, float* __restrict__ lout)
{
    int gid = blockIdx.x;
    int j = gid % SELN;
    int h = (gid / SELN) % H_;
    int b = gid / (SELN * H_);

    __shared__ float q[HD_];
    __shared__ float sc[N_];
    __shared__ float red[128];

    int t = threadIdx.x;
    const float scale = 0.125f; // 64^-0.5

    const float* qrow = qsel + ((size_t)(b * SELN + j)) * D_ + h * HD_;
    if (t < HD_) q[t] = qrow[t];
    __syncthreads();

    // scores: one warp per key
    int warp = t >> 5, lane = t & 31;
    for (int n = warp; n < N_; n += 4) {
        const float* krow = kall + ((size_t)b * N_ + n) * D_ + h * HD_;
        float s = q[lane] * krow[lane] + q[lane + 32] * krow[lane + 32];
#pragma unroll
        for (int o = 16; o > 0; o >>= 1) s += __shfl_xor_sync(0xffffffffu, s, o);
        if (lane == 0) sc[n] = s * scale;
    }
    __syncthreads();

    // softmax
    float mx = -CUDART_INF_F;
    for (int n = t; n < N_; n += 128) mx = fmaxf(mx, sc[n]);
    red[t] = mx; __syncthreads();
    for (int s = 64; s > 0; s >>= 1) {
        if (t < s) red[t] = fmaxf(red[t], red[t + s]);
        __syncthreads();
    }
    mx = red[0];
    __syncthreads();
    float sum = 0.f;
    for (int n = t; n < N_; n += 128) { float e = expf(sc[n] - mx); sc[n] = e; sum += e; }
    red[t] = sum; __syncthreads();
    for (int s = 64; s > 0; s >>= 1) {
        if (t < s) red[t] += red[t + s];
        __syncthreads();
    }
    float inv = 1.f / red[0];
    __syncthreads();

    // out[d] = sum_n p[n] * v[n][d]
    int d = t & 63, half = t >> 6;
    float acc = 0.f;
    const float* vbase = vall + (size_t)b * N_ * D_ + h * HD_ + d;
    for (int n = half; n < N_; n += 2) acc += sc[n] * vbase[(size_t)n * D_];
    red[t] = acc; __syncthreads();
    if (t < 64) {
        float o = (red[t] + red[t + 64]) * inv;
        lout[((size_t)(b * SELN + j)) * D_ + h * HD_ + t] = o;
    }
}

// ---------------- host launcher -----------------------------------------------
extern "C" void kernel_launch(void* const* d_in, const int* in_sizes, int n_in,
                              void* d_out, int out_size) {
    const float* x      = (const float*)d_in[0];
    const float* accatt = (const float*)d_in[1];
    const float* q_w    = (const float*)d_in[2];
    const float* k_w    = (const float*)d_in[3];
    const float* v_w    = (const float*)d_in[4];
    const float* proj_w = (const float*)d_in[5];
    const float* proj_b = (const float*)d_in[6];
    float* out = (float*)d_out;

    int*   sel;  cudaGetSymbolAddress((void**)&sel,  g_sel);
    float* xsel; cudaGetSymbolAddress((void**)&xsel, g_xsel);
    float* qsel; cudaGetSymbolAddress((void**)&qsel, g_qsel);
    float* kall; cudaGetSymbolAddress((void**)&kall, g_kall);
    float* vall; cudaGetSymbolAddress((void**)&vall, g_vall);
    float* lout; cudaGetSymbolAddress((void**)&lout, g_lout);
    float* y;    cudaGetSymbolAddress((void**)&y,    g_y);

    // 1. top-k selection
    topk_kernel<<<B_, 256>>>(accatt, sel);

    // 2. gather selected rows of x
    gather_rows_kernel<<<M_SEL, 128>>>(x, sel, xsel);

    // 3. K, V over all rows; Q over selected rows
    dim3 gAll(D_ / GBN, (M_ALL + GBM - 1) / GBM);
    dim3 gSel(D_ / GBN, (M_SEL + GBM - 1) / GBM);
    gemm_tn_kernel<<<gAll, 256>>>(x, k_w, nullptr, kall, M_ALL, D_, D_);
    gemm_tn_kernel<<<gAll, 256>>>(x, v_w, nullptr, vall, M_ALL, D_, D_);
    gemm_tn_kernel<<<gSel, 256>>>(xsel, q_w, nullptr, qsel, M_SEL, D_, D_);

    // 4. attention over selected queries
    attn_kernel<<<B_ * H_ * SELN, 128>>>(qsel, kall, vall, lout);

    // 5. y = x; y[selected rows] = local_out
    copy_kernel<<<2048, 256>>>(x, y, (size_t)M_ALL * D_ / 4);
    scatter_rows_kernel<<<M_SEL, 128>>>(lout, sel, y);

    // 6. final projection with bias -> d_out
    gemm_tn_kernel<<<gAll, 256>>>(y, proj_w, proj_b, out, M_ALL, D_, D_);
}

// round 3
// speedup vs baseline: 2.1862x; 2.1862x over previous
#include <cuda_runtime.h>
#include <cuda_bf16.h>
#include <cstdint>
#include <math_constants.h>

// ---------------- problem constants ----------------
#define B_   64
#define N_   577
#define D_   768
#define H_   12
#define HD_  64
#define KK_  57
#define SELN 58
#define M_ALL (B_ * N_)    // 36928
#define M_SEL (B_ * SELN)  // 3712

// ---------------- scratch ----------------
__device__ int   g_sel[M_SEL];
__device__ __nv_bfloat16 g_xhi[(size_t)M_ALL * D_];
__device__ __nv_bfloat16 g_xlo[(size_t)M_ALL * D_];
__device__ __nv_bfloat16 g_xselhi[(size_t)M_SEL * D_];
__device__ __nv_bfloat16 g_xsello[(size_t)M_SEL * D_];
__device__ __nv_bfloat16 g_kwh[D_ * D_], g_kwl[D_ * D_];
__device__ __nv_bfloat16 g_vwh[D_ * D_], g_vwl[D_ * D_];
__device__ __nv_bfloat16 g_qwh[D_ * D_], g_qwl[D_ * D_];
__device__ __nv_bfloat16 g_pwh[D_ * D_], g_pwl[D_ * D_];
__device__ float g_qsel[(size_t)M_SEL * D_];
__device__ float g_kall[(size_t)M_ALL * D_];
__device__ float g_vall[(size_t)M_ALL * D_];

// ---------------- helpers ----------------
__device__ __forceinline__ uint32_t smem_u32(const void* p) {
    uint32_t a;
    asm("{ .reg .u64 t; cvta.to.shared.u64 t, %1; cvt.u32.u64 %0, t; }" : "=r"(a) : "l"(p));
    return a;
}
__device__ __forceinline__ uint32_t pack_bf16(__nv_bfloat16 a, __nv_bfloat16 b) {
    __nv_bfloat162 t(a, b);
    return *reinterpret_cast<uint32_t*>(&t);
}
__device__ __forceinline__ void cp16(uint32_t dst, const void* src, uint32_t sz) {
    asm volatile("cp.async.cg.shared.global [%0], [%1], 16, %2;" :: "r"(dst), "l"(src), "r"(sz) : "memory");
}
#define CP_COMMIT() asm volatile("cp.async.commit_group;" ::: "memory")
#define CP_WAIT0()  asm volatile("cp.async.wait_group 0;" ::: "memory")
#define CP_WAIT1()  asm volatile("cp.async.wait_group 1;" ::: "memory")

__device__ __forceinline__ void ldsm4(uint32_t* r, uint32_t addr) {
    asm volatile("ldmatrix.sync.aligned.m8n8.x4.shared.b16 {%0,%1,%2,%3}, [%4];"
        : "=r"(r[0]), "=r"(r[1]), "=r"(r[2]), "=r"(r[3]) : "r"(addr));
}
__device__ __forceinline__ void mma16816(float* d, const uint32_t* a, const uint32_t* b) {
    asm volatile(
        "mma.sync.aligned.m16n8k16.row.col.f32.bf16.bf16.f32 "
        "{%0,%1,%2,%3}, {%4,%5,%6,%7}, {%8,%9}, {%0,%1,%2,%3};"
        : "+f"(d[0]), "+f"(d[1]), "+f"(d[2]), "+f"(d[3])
        : "r"(a[0]), "r"(a[1]), "r"(a[2]), "r"(a[3]), "r"(b[0]), "r"(b[1]));
}

// ---------------- split fp32 -> bf16 hi/lo ----------------
__global__ void split_kernel(const float4* __restrict__ src, uint2* __restrict__ hi,
                             uint2* __restrict__ lo, int n4) {
    int i = blockIdx.x * blockDim.x + threadIdx.x;
    int stride = gridDim.x * blockDim.x;
    for (; i < n4; i += stride) {
        float4 v = src[i];
        __nv_bfloat16 h0 = __float2bfloat16(v.x), h1 = __float2bfloat16(v.y);
        __nv_bfloat16 h2 = __float2bfloat16(v.z), h3 = __float2bfloat16(v.w);
        __nv_bfloat16 l0 = __float2bfloat16(v.x - __bfloat162float(h0));
        __nv_bfloat16 l1 = __float2bfloat16(v.y - __bfloat162float(h1));
        __nv_bfloat16 l2 = __float2bfloat16(v.z - __bfloat162float(h2));
        __nv_bfloat16 l3 = __float2bfloat16(v.w - __bfloat162float(h3));
        uint2 H; H.x = pack_bf16(h0, h1); H.y = pack_bf16(h2, h3);
        uint2 L; L.x = pack_bf16(l0, l1); L.y = pack_bf16(l2, l3);
        hi[i] = H; lo[i] = L;
    }
}

// ---------------- top-k (iterative argmax, one block per batch) ----------------
__global__ void topk_kernel(const float* __restrict__ acc, int* __restrict__ sel) {
    int b = blockIdx.x;
    __shared__ float vals[N_ - 1];
    __shared__ float rv[256];
    __shared__ int   ri[256];
    int t = threadIdx.x;
    const float* src = acc + (size_t)b * N_ * N_ + 1;
    for (int i = t; i < N_ - 1; i += 256) vals[i] = src[i];
    if (t == 0) sel[b * SELN] = 0;
    __syncthreads();
    for (int it = 0; it < KK_; it++) {
        float best = -CUDART_INF_F; int bi = 0;
        for (int i = t; i < N_ - 1; i += 256) {
            float v = vals[i];
            if (v > best) { best = v; bi = i; }
        }
        rv[t] = best; ri[t] = bi;
        __syncthreads();
        for (int s = 128; s > 0; s >>= 1) {
            if (t < s && rv[t + s] > rv[t]) { rv[t] = rv[t + s]; ri[t] = ri[t + s]; }
            __syncthreads();
        }
        if (t == 0) { sel[b * SELN + 1 + it] = ri[0] + 1; vals[ri[0]] = -CUDART_INF_F; }
        __syncthreads();
    }
}

// ---------------- gather selected bf16 rows ----------------
__global__ void gather_kernel(const __nv_bfloat16* __restrict__ xhi, const __nv_bfloat16* __restrict__ xlo,
                              const int* __restrict__ sel,
                              __nv_bfloat16* __restrict__ dhi, __nv_bfloat16* __restrict__ dlo) {
    int m = blockIdx.x;
    int b = m / SELN;
    int tok = sel[m];
    const uint4* sh = (const uint4*)(xhi + ((size_t)(b * N_ + tok)) * D_);
    const uint4* sl = (const uint4*)(xlo + ((size_t)(b * N_ + tok)) * D_);
    uint4* th = (uint4*)(dhi + (size_t)m * D_);
    uint4* tl = (uint4*)(dlo + (size_t)m * D_);
    int i = threadIdx.x;
    if (i < 96) { th[i] = sh[i]; tl[i] = sl[i]; }
}

// ---------------- HMMA split-bf16 GEMM ----------------
// C[m, col0+c] = sum_k A[m,k]*B[col0+c,k] (+bias). A=Ahi+Alo, B=Bhi+Blo.
// BM=128 BN=128 BK=32, 256 threads = 8 warps (2 m x 4 n), warp tile 64x32.
// smem per stage: Ahi/Alo/Bhi/Blo, each 128 rows x 80B (64B data + 16B pad).
#define GST 40960
#define GSMEM (2 * GST)
#define KITERS (D_ / 32)   // 24

__global__ __launch_bounds__(256) void gemm_kernel(
    const __nv_bfloat16* __restrict__ Ahi, const __nv_bfloat16* __restrict__ Alo,
    const __nv_bfloat16* __restrict__ Bhi0, const __nv_bfloat16* __restrict__ Blo0,
    const __nv_bfloat16* __restrict__ Bhi1, const __nv_bfloat16* __restrict__ Blo1,
    const float* __restrict__ bias, float* __restrict__ C0, float* __restrict__ C1,
    int M, int nsplit)
{
    extern __shared__ char smem[];
    uint32_t sb = smem_u32(smem);
    int tid = threadIdx.x;
    int lane = tid & 31;
    int wid = tid >> 5;
    int wm = wid & 1, wn = wid >> 1;
    int bx = blockIdx.x, by = blockIdx.y;

    const __nv_bfloat16 *Bhi, *Blo; float* C; int nb;
    if (bx < nsplit) { Bhi = Bhi0; Blo = Blo0; C = C0; nb = bx; }
    else             { Bhi = Bhi1; Blo = Blo1; C = C1; nb = bx - nsplit; }
    int col0 = nb * 128;
    int row0 = by * 128;

    float acc[4][4][4];
#pragma unroll
    for (int i = 0; i < 4; i++)
#pragma unroll
        for (int j = 0; j < 4; j++)
#pragma unroll
            for (int r = 0; r < 4; r++) acc[i][j][r] = 0.f;

    int lr = tid >> 2;       // 0..63 base row pair index
    int lc = tid & 3;        // chunk

    auto load_stage = [&](int buf, int k0) {
        uint32_t base = sb + buf * GST;
#pragma unroll
        for (int i = 0; i < 2; i++) {
            int r = lr + i * 64;
            int gm = row0 + r;
            uint32_t sz = (gm < M) ? 16u : 0u;
            int cg = gm < M ? gm : (M - 1);
            size_t off = (size_t)cg * D_ + k0 + lc * 8;
            uint32_t sa = base + r * 80 + lc * 16;
            cp16(sa, Ahi + off, sz);
            cp16(sa + 10240, Alo + off, sz);
            size_t ob = (size_t)(col0 + r) * D_ + k0 + lc * 8;
            uint32_t sbn = base + 20480 + r * 80 + lc * 16;
            cp16(sbn, Bhi + ob, 16u);
            cp16(sbn + 10240, Blo + ob, 16u);
        }
    };

    load_stage(0, 0);
    CP_COMMIT();

    for (int it = 0; it < KITERS; it++) {
        int buf = it & 1;
        if (it + 1 < KITERS) {
            load_stage(buf ^ 1, (it + 1) * 32);
            CP_COMMIT();
            CP_WAIT1();
        } else {
            CP_WAIT0();
        }
        __syncthreads();

        uint32_t stg = sb + buf * GST;
        uint32_t a_addr0 = stg + (uint32_t)(wm * 64 + (lane & 15)) * 80 + (uint32_t)(lane >> 4) * 16;
        uint32_t b_addr0 = stg + 20480 +
            (uint32_t)(wn * 32 + ((lane >> 4) & 1) * 8 + (lane & 7)) * 80 +
            (uint32_t)((lane >> 3) & 1) * 16;

#pragma unroll
        for (int ks = 0; ks < 2; ks++) {
            uint32_t ah[4][4], al[4][4], bh[4][2], bl[4][2];
#pragma unroll
            for (int i = 0; i < 4; i++) {
                uint32_t ad = a_addr0 + (uint32_t)(i * 16 * 80) + (uint32_t)(ks * 32);
                ldsm4(ah[i], ad);
                ldsm4(al[i], ad + 10240);
            }
#pragma unroll
            for (int p = 0; p < 2; p++) {
                uint32_t bd = b_addr0 + (uint32_t)(p * 16 * 80) + (uint32_t)(ks * 32);
                uint32_t tmp[4];
                ldsm4(tmp, bd);
                bh[p * 2 + 0][0] = tmp[0]; bh[p * 2 + 0][1] = tmp[1];
                bh[p * 2 + 1][0] = tmp[2]; bh[p * 2 + 1][1] = tmp[3];
                ldsm4(tmp, bd + 10240);
                bl[p * 2 + 0][0] = tmp[0]; bl[p * 2 + 0][1] = tmp[1];
                bl[p * 2 + 1][0] = tmp[2]; bl[p * 2 + 1][1] = tmp[3];
            }
#pragma unroll
            for (int i = 0; i < 4; i++)
#pragma unroll
                for (int j = 0; j < 4; j++)
                    mma16816(acc[i][j], ah[i], bh[j]);
#pragma unroll
            for (int i = 0; i < 4; i++)
#pragma unroll
                for (int j = 0; j < 4; j++)
                    mma16816(acc[i][j], ah[i], bl[j]);
#pragma unroll
            for (int i = 0; i < 4; i++)
#pragma unroll
                for (int j = 0; j < 4; j++)
                    mma16816(acc[i][j], al[i], bh[j]);
        }
        __syncthreads();
    }

    // epilogue
#pragma unroll
    for (int i = 0; i < 4; i++) {
        int r0g = row0 + wm * 64 + i * 16 + (lane >> 2);
        int r1g = r0g + 8;
#pragma unroll
        for (int j = 0; j < 4; j++) {
            int col = col0 + wn * 32 + j * 8 + (lane & 3) * 2;
            float b0 = 0.f, b1 = 0.f;
            if (bias) { b0 = bias[col]; b1 = bias[col + 1]; }
            if (r0g < M) {
                float2 o; o.x = acc[i][j][0] + b0; o.y = acc[i][j][1] + b1;
                *(float2*)(C + (size_t)r0g * D_ + col) = o;
            }
            if (r1g < M) {
                float2 o; o.x = acc[i][j][2] + b0; o.y = acc[i][j][3] + b1;
                *(float2*)(C + (size_t)r1g * D_ + col) = o;
            }
        }
    }
}

// ---------------- attention: one block per (b, h), 58 queries ----------------
#define ATTN_SMEM_FLOATS (N_ * 64 + 64 * 64 + 64 + 64 + 256)
#define ATTN_SMEM_BYTES  (ATTN_SMEM_FLOATS * 4)

__global__ __launch_bounds__(256) void attn_kernel(
    const float* __restrict__ qsel, const float* __restrict__ kall,
    const float* __restrict__ vall, const int* __restrict__ sel,
    __nv_bfloat16* __restrict__ yhi, __nv_bfloat16* __restrict__ ylo)
{
    extern __shared__ float sm[];
    float* P    = sm;                   // [577][64]
    float* Ks   = P + N_ * 64;          // [64][64]
    float* mx   = Ks + 64 * 64;         // [64]
    float* sums = mx + 64;              // [64]
    float* red  = sums + 64;            // [4][64]

    int bh = blockIdx.x;
    int h = bh % H_;
    int b = bh / H_;
    int t = threadIdx.x;
    int j = t & 63;
    int g = t >> 6;

    float4 q4[16];
    if (j < SELN) {
        const float4* qr = (const float4*)(qsel + ((size_t)(b * SELN + j)) * D_ + h * HD_);
#pragma unroll
        for (int i = 0; i < 16; i++) q4[i] = qr[i];
    } else {
#pragma unroll
        for (int i = 0; i < 16; i++) q4[i] = make_float4(0.f, 0.f, 0.f, 0.f);
    }

    // scores
    for (int n0 = 0; n0 < N_; n0 += 64) {
        int nend = min(64, N_ - n0);
        __syncthreads();
        for (int idx = t; idx < nend * 16; idx += 256) {
            int r = idx >> 4, cc = idx & 15;
            ((float4*)Ks)[r * 16 + cc] =
                *(const float4*)(kall + ((size_t)(b * N_ + n0 + r)) * D_ + h * HD_ + cc * 4);
        }
        __syncthreads();
#pragma unroll
        for (int i = 0; i < 16; i++) {
            int n = g * 16 + i;
            if (n < nend) {
                const float4* kr = (const float4*)(Ks + n * 64);
                float s = 0.f;
#pragma unroll
                for (int d = 0; d < 16; d++) {
                    float4 k = kr[d];
                    s += q4[d].x * k.x + q4[d].y * k.y + q4[d].z * k.z + q4[d].w * k.w;
                }
                P[(n0 + n) * 64 + j] = s * 0.125f;
            }
        }
    }
    __syncthreads();

    // softmax over keys per query j
    float m = -CUDART_INF_F;
    for (int n = g; n < N_; n += 4) m = fmaxf(m, P[n * 64 + j]);
    red[g * 64 + j] = m;
    __syncthreads();
    if (g == 0) mx[j] = fmaxf(fmaxf(red[j], red[64 + j]), fmaxf(red[128 + j], red[192 + j]));
    __syncthreads();
    float mm = mx[j];
    float ssum = 0.f;
    for (int n = g; n < N_; n += 4) {
        float e = __expf(P[n * 64 + j] - mm);
        P[n * 64 + j] = e;
        ssum += e;
    }
    red[g * 64 + j] = ssum;
    __syncthreads();
    if (g == 0) sums[j] = red[j] + red[64 + j] + red[128 + j] + red[192 + j];
    __syncthreads();
    float inv = 1.f / sums[j];

    // O = P @ V
    float4 o0 = make_float4(0.f, 0.f, 0.f, 0.f), o1 = o0, o2 = o0, o3 = o0;
    for (int n0 = 0; n0 < N_; n0 += 64) {
        int nend = min(64, N_ - n0);
        __syncthreads();
        for (int idx = t; idx < nend * 16; idx += 256) {
            int r = idx >> 4, cc = idx & 15;
            ((float4*)Ks)[r * 16 + cc] =
                *(const float4*)(vall + ((size_t)(b * N_ + n0 + r)) * D_ + h * HD_ + cc * 4);
        }
        __syncthreads();
        for (int n = 0; n < nend; n++) {
            float p = P[(n0 + n) * 64 + j];
            const float4* vr = (const float4*)(Ks + n * 64 + g * 16);
            float4 v0 = vr[0], v1 = vr[1], v2 = vr[2], v3 = vr[3];
            o0.x += p * v0.x; o0.y += p * v0.y; o0.z += p * v0.z; o0.w += p * v0.w;
            o1.x += p * v1.x; o1.y += p * v1.y; o1.z += p * v1.z; o1.w += p * v1.w;
            o2.x += p * v2.x; o2.y += p * v2.y; o2.z += p * v2.z; o2.w += p * v2.w;
            o3.x += p * v3.x; o3.y += p * v3.y; o3.z += p * v3.z; o3.w += p * v3.w;
        }
    }

    if (j < SELN) {
        int tok = sel[b * SELN + j];
        size_t base = ((size_t)(b * N_ + tok)) * D_ + h * HD_ + g * 16;
        float vals[16];
        vals[0] = o0.x * inv; vals[1] = o0.y * inv; vals[2] = o0.z * inv; vals[3] = o0.w * inv;
        vals[4] = o1.x * inv; vals[5] = o1.y * inv; vals[6] = o1.z * inv; vals[7] = o1.w * inv;
        vals[8] = o2.x * inv; vals[9] = o2.y * inv; vals[10] = o2.z * inv; vals[11] = o2.w * inv;
        vals[12] = o3.x * inv; vals[13] = o3.y * inv; vals[14] = o3.z * inv; vals[15] = o3.w * inv;
        uint32_t* ph = (uint32_t*)(yhi + base);
        uint32_t* pl = (uint32_t*)(ylo + base);
#pragma unroll
        for (int p2 = 0; p2 < 8; p2++) {
            float a = vals[2 * p2], bv = vals[2 * p2 + 1];
            __nv_bfloat16 ha = __float2bfloat16(a), hb = __float2bfloat16(bv);
            __nv_bfloat16 la = __float2bfloat16(a - __bfloat162float(ha));
            __nv_bfloat16 lb = __float2bfloat16(bv - __bfloat162float(hb));
            ph[p2] = pack_bf16(ha, hb);
            pl[p2] = pack_bf16(la, lb);
        }
    }
}

// ---------------- host launcher ----------------
extern "C" void kernel_launch(void* const* d_in, const int* in_sizes, int n_in,
                              void* d_out, int out_size) {
    const float* x      = (const float*)d_in[0];
    const float* accatt = (const float*)d_in[1];
    const float* q_w    = (const float*)d_in[2];
    const float* k_w    = (const float*)d_in[3];
    const float* v_w    = (const float*)d_in[4];
    const float* proj_w = (const float*)d_in[5];
    const float* proj_b = (const float*)d_in[6];
    float* out = (float*)d_out;

    int* sel; cudaGetSymbolAddress((void**)&sel, g_sel);
    __nv_bfloat16 *xhi, *xlo, *xselhi, *xsello;
    __nv_bfloat16 *kwh, *kwl, *vwh, *vwl, *qwh, *qwl, *pwh, *pwl;
    float *qsel, *kall, *vall;
    cudaGetSymbolAddress((void**)&xhi, g_xhi);   cudaGetSymbolAddress((void**)&xlo, g_xlo);
    cudaGetSymbolAddress((void**)&xselhi, g_xselhi); cudaGetSymbolAddress((void**)&xsello, g_xsello);
    cudaGetSymbolAddress((void**)&kwh, g_kwh);   cudaGetSymbolAddress((void**)&kwl, g_kwl);
    cudaGetSymbolAddress((void**)&vwh, g_vwh);   cudaGetSymbolAddress((void**)&vwl, g_vwl);
    cudaGetSymbolAddress((void**)&qwh, g_qwh);   cudaGetSymbolAddress((void**)&qwl, g_qwl);
    cudaGetSymbolAddress((void**)&pwh, g_pwh);   cudaGetSymbolAddress((void**)&pwl, g_pwl);
    cudaGetSymbolAddress((void**)&qsel, g_qsel);
    cudaGetSymbolAddress((void**)&kall, g_kall); cudaGetSymbolAddress((void**)&vall, g_vall);

    cudaFuncSetAttribute(gemm_kernel, cudaFuncAttributeMaxDynamicSharedMemorySize, GSMEM);
    cudaFuncSetAttribute(attn_kernel, cudaFuncAttributeMaxDynamicSharedMemorySize, ATTN_SMEM_BYTES);

    const int NX4 = M_ALL * D_ / 4;
    const int NW4 = D_ * D_ / 4;

    // splits
    split_kernel<<<4096, 256>>>((const float4*)x, (uint2*)xhi, (uint2*)xlo, NX4);
    split_kernel<<<512, 256>>>((const float4*)k_w, (uint2*)kwh, (uint2*)kwl, NW4);
    split_kernel<<<512, 256>>>((const float4*)v_w, (uint2*)vwh, (uint2*)vwl, NW4);
    split_kernel<<<512, 256>>>((const float4*)q_w, (uint2*)qwh, (uint2*)qwl, NW4);
    split_kernel<<<512, 256>>>((const float4*)proj_w, (uint2*)pwh, (uint2*)pwl, NW4);

    // selection + gather
    topk_kernel<<<B_, 256>>>(accatt, sel);
    gather_kernel<<<M_SEL, 128>>>(xhi, xlo, sel, xselhi, xsello);

    // K, V (fused) and Q GEMMs
    gemm_kernel<<<dim3(12, 289), 256, GSMEM>>>(xhi, xlo, kwh, kwl, vwh, vwl,
                                               nullptr, kall, vall, M_ALL, 6);
    gemm_kernel<<<dim3(6, 29), 256, GSMEM>>>(xselhi, xsello, qwh, qwl, qwh, qwl,
                                             nullptr, qsel, qsel, M_SEL, 6);

    // attention scatters split-bf16 output directly into xhi/xlo
    attn_kernel<<<B_ * H_, 256, ATTN_SMEM_BYTES>>>(qsel, kall, vall, sel, xhi, xlo);

    // final projection (reads updated xhi/xlo)
    gemm_kernel<<<dim3(6, 289), 256, GSMEM>>>(xhi, xlo, pwh, pwl, pwh, pwl,
                                              proj_b, out, out, M_ALL, 6);
}

// round 4
// speedup vs baseline: 2.4085x; 1.1017x over previous
#include <cuda_runtime.h>
#include <cuda_bf16.h>
#include <cstdint>
#include <math_constants.h>

// ---------------- problem constants ----------------
#define B_   64
#define N_   577
#define D_   768
#define H_   12
#define HD_  64
#define KK_  57
#define SELN 58
#define M_ALL (B_ * N_)    // 36928
#define M_SEL (B_ * SELN)  // 3712

// ---------------- scratch ----------------
__device__ int   g_sel[M_SEL];
__device__ __nv_bfloat16 g_xhi[(size_t)M_ALL * D_];
__device__ __nv_bfloat16 g_xlo[(size_t)M_ALL * D_];
__device__ __nv_bfloat16 g_xselhi[(size_t)M_SEL * D_];
__device__ __nv_bfloat16 g_xsello[(size_t)M_SEL * D_];
__device__ __nv_bfloat16 g_kwh[D_ * D_], g_kwl[D_ * D_];
__device__ __nv_bfloat16 g_vwh[D_ * D_], g_vwl[D_ * D_];
__device__ __nv_bfloat16 g_qwh[D_ * D_], g_qwl[D_ * D_];
__device__ __nv_bfloat16 g_pwh[D_ * D_], g_pwl[D_ * D_];
__device__ float g_qsel[(size_t)M_SEL * D_];
__device__ float g_kall[(size_t)M_ALL * D_];
__device__ float g_vall[(size_t)M_ALL * D_];

// ---------------- helpers ----------------
__device__ __forceinline__ uint32_t smem_u32(const void* p) {
    uint32_t a;
    asm("{ .reg .u64 t; cvta.to.shared.u64 t, %1; cvt.u32.u64 %0, t; }" : "=r"(a) : "l"(p));
    return a;
}
__device__ __forceinline__ uint32_t pack_bf16(__nv_bfloat16 a, __nv_bfloat16 b) {
    __nv_bfloat162 t(a, b);
    return *reinterpret_cast<uint32_t*>(&t);
}
__device__ __forceinline__ void cp16(uint32_t dst, const void* src, uint32_t sz) {
    asm volatile("cp.async.cg.shared.global [%0], [%1], 16, %2;" :: "r"(dst), "l"(src), "r"(sz) : "memory");
}
#define CP_COMMIT() asm volatile("cp.async.commit_group;" ::: "memory")
#define CP_WAIT0()  asm volatile("cp.async.wait_group 0;" ::: "memory")
#define CP_WAIT1()  asm volatile("cp.async.wait_group 1;" ::: "memory")

__device__ __forceinline__ void ldsm4(uint32_t* r, uint32_t addr) {
    asm volatile("ldmatrix.sync.aligned.m8n8.x4.shared.b16 {%0,%1,%2,%3}, [%4];"
        : "=r"(r[0]), "=r"(r[1]), "=r"(r[2]), "=r"(r[3]) : "r"(addr));
}
__device__ __forceinline__ void mma16816(float* d, const uint32_t* a, const uint32_t* b) {
    asm volatile(
        "mma.sync.aligned.m16n8k16.row.col.f32.bf16.bf16.f32 "
        "{%0,%1,%2,%3}, {%4,%5,%6,%7}, {%8,%9}, {%0,%1,%2,%3};"
        : "+f"(d[0]), "+f"(d[1]), "+f"(d[2]), "+f"(d[3])
        : "r"(a[0]), "r"(a[1]), "r"(a[2]), "r"(a[3]), "r"(b[0]), "r"(b[1]));
}

// ---------------- split fp32 -> bf16 hi/lo ----------------
__device__ __forceinline__ void split4(float4 v, uint2& H, uint2& L) {
    __nv_bfloat16 h0 = __float2bfloat16(v.x), h1 = __float2bfloat16(v.y);
    __nv_bfloat16 h2 = __float2bfloat16(v.z), h3 = __float2bfloat16(v.w);
    __nv_bfloat16 l0 = __float2bfloat16(v.x - __bfloat162float(h0));
    __nv_bfloat16 l1 = __float2bfloat16(v.y - __bfloat162float(h1));
    __nv_bfloat16 l2 = __float2bfloat16(v.z - __bfloat162float(h2));
    __nv_bfloat16 l3 = __float2bfloat16(v.w - __bfloat162float(h3));
    H.x = pack_bf16(h0, h1); H.y = pack_bf16(h2, h3);
    L.x = pack_bf16(l0, l1); L.y = pack_bf16(l2, l3);
}
__global__ void split_kernel(const float4* __restrict__ src, uint2* __restrict__ hi,
                             uint2* __restrict__ lo, int n4) {
    int i = blockIdx.x * blockDim.x + threadIdx.x;
    int stride = gridDim.x * blockDim.x;
    for (; i < n4; i += stride) {
        uint2 H, L;
        split4(src[i], H, L);
        hi[i] = H; lo[i] = L;
    }
}
// all 4 weight splits in one launch: blocks [s*512, (s+1)*512) handle weight s
__global__ void split_w_kernel(const float4* w0, uint2* h0, uint2* l0,
                               const float4* w1, uint2* h1, uint2* l1,
                               const float4* w2, uint2* h2, uint2* l2,
                               const float4* w3, uint2* h3, uint2* l3) {
    int s = blockIdx.x >> 9;
    int local = blockIdx.x & 511;
    const float4* src = s == 0 ? w0 : s == 1 ? w1 : s == 2 ? w2 : w3;
    uint2* hi = s == 0 ? h0 : s == 1 ? h1 : s == 2 ? h2 : h3;
    uint2* lo = s == 0 ? l0 : s == 1 ? l1 : s == 2 ? l2 : l3;
    const int n4 = D_ * D_ / 4;
    for (int i = local * 256 + threadIdx.x; i < n4; i += 512 * 256) {
        uint2 H, L;
        split4(src[i], H, L);
        hi[i] = H; lo[i] = L;
    }
}

// ---------------- top-k (iterative argmax, one block per batch) ----------------
__global__ void topk_kernel(const float* __restrict__ acc, int* __restrict__ sel) {
    int b = blockIdx.x;
    __shared__ float vals[N_ - 1];
    __shared__ float rv[256];
    __shared__ int   ri[256];
    int t = threadIdx.x;
    const float* src = acc + (size_t)b * N_ * N_ + 1;
    for (int i = t; i < N_ - 1; i += 256) vals[i] = src[i];
    if (t == 0) sel[b * SELN] = 0;
    __syncthreads();
    for (int it = 0; it < KK_; it++) {
        float best = -CUDART_INF_F; int bi = 0;
        for (int i = t; i < N_ - 1; i += 256) {
            float v = vals[i];
            if (v > best) { best = v; bi = i; }
        }
        rv[t] = best; ri[t] = bi;
        __syncthreads();
        for (int s = 128; s > 0; s >>= 1) {
            if (t < s && rv[t + s] > rv[t]) { rv[t] = rv[t + s]; ri[t] = ri[t + s]; }
            __syncthreads();
        }
        if (t == 0) { sel[b * SELN + 1 + it] = ri[0] + 1; vals[ri[0]] = -CUDART_INF_F; }
        __syncthreads();
    }
}

// ---------------- gather selected bf16 rows ----------------
__global__ void gather_kernel(const __nv_bfloat16* __restrict__ xhi, const __nv_bfloat16* __restrict__ xlo,
                              const int* __restrict__ sel,
                              __nv_bfloat16* __restrict__ dhi, __nv_bfloat16* __restrict__ dlo) {
    int m = blockIdx.x;
    int b = m / SELN;
    int tok = sel[m];
    const uint4* sh = (const uint4*)(xhi + ((size_t)(b * N_ + tok)) * D_);
    const uint4* sl = (const uint4*)(xlo + ((size_t)(b * N_ + tok)) * D_);
    uint4* th = (uint4*)(dhi + (size_t)m * D_);
    uint4* tl = (uint4*)(dlo + (size_t)m * D_);
    int i = threadIdx.x;
    if (i < 96) { th[i] = sh[i]; tl[i] = sl[i]; }
}

// ---------------- HMMA split-bf16 GEMM ----------------
// Segmented along grid.x: segment s = bx/per, weight/output per segment.
// C[m, col0+c] = sum_k A[m,k]*B[col0+c,k] (+bias). A=Ahi+Alo, B=Bhi+Blo.
// BM=128 BN=128 BK=32, 256 threads = 8 warps (2 m x 4 n), warp tile 64x32.
// If selmap != null, output row m is remapped to (m/SELN)*N_ + selmap[m].
struct Seg {
    const __nv_bfloat16* bh;
    const __nv_bfloat16* bl;
    float* c;
    const float* bias;
};
#define GST 40960
#define GSMEM (2 * GST)
#define KITERS (D_ / 32)   // 24

__global__ __launch_bounds__(256) void gemm_kernel(
    const __nv_bfloat16* __restrict__ Ahi, const __nv_bfloat16* __restrict__ Alo,
    Seg s0, Seg s1, Seg s2,
    int M, int per, const int* __restrict__ selmap)
{
    extern __shared__ char smem[];
    uint32_t sb = smem_u32(smem);
    int tid = threadIdx.x;
    int lane = tid & 31;
    int wid = tid >> 5;
    int wm = wid & 1, wn = wid >> 1;
    int bx = blockIdx.x, by = blockIdx.y;

    int seg = bx / per;
    Seg S = (seg == 0) ? s0 : (seg == 1) ? s1 : s2;
    int nb = bx - seg * per;
    const __nv_bfloat16* Bhi = S.bh;
    const __nv_bfloat16* Blo = S.bl;
    float* C = S.c;
    const float* bias = S.bias;
    int col0 = nb * 128;
    int row0 = by * 128;

    float acc[4][4][4];
#pragma unroll
    for (int i = 0; i < 4; i++)
#pragma unroll
        for (int j = 0; j < 4; j++)
#pragma unroll
            for (int r = 0; r < 4; r++) acc[i][j][r] = 0.f;

    int lr = tid >> 2;       // 0..63
    int lc = tid & 3;        // 16B chunk

    auto load_stage = [&](int buf, int k0) {
        uint32_t base = sb + buf * GST;
#pragma unroll
        for (int i = 0; i < 2; i++) {
            int r = lr + i * 64;
            int gm = row0 + r;
            uint32_t sz = (gm < M) ? 16u : 0u;
            int cg = gm < M ? gm : (M - 1);
            size_t off = (size_t)cg * D_ + k0 + lc * 8;
            uint32_t sa = base + r * 80 + lc * 16;
            cp16(sa, Ahi + off, sz);
            cp16(sa + 10240, Alo + off, sz);
            size_t ob = (size_t)(col0 + r) * D_ + k0 + lc * 8;
            uint32_t sbn = base + 20480 + r * 80 + lc * 16;
            cp16(sbn, Bhi + ob, 16u);
            cp16(sbn + 10240, Blo + ob, 16u);
        }
    };

    load_stage(0, 0);
    CP_COMMIT();

    for (int it = 0; it < KITERS; it++) {
        int buf = it & 1;
        if (it + 1 < KITERS) {
            load_stage(buf ^ 1, (it + 1) * 32);
            CP_COMMIT();
            CP_WAIT1();
        } else {
            CP_WAIT0();
        }
        __syncthreads();

        uint32_t stg = sb + buf * GST;
        uint32_t a_addr0 = stg + (uint32_t)(wm * 64 + (lane & 15)) * 80 + (uint32_t)(lane >> 4) * 16;
        uint32_t b_addr0 = stg + 20480 +
            (uint32_t)(wn * 32 + ((lane >> 4) & 1) * 8 + (lane & 7)) * 80 +
            (uint32_t)((lane >> 3) & 1) * 16;

#pragma unroll
        for (int ks = 0; ks < 2; ks++) {
            uint32_t ah[4][4], al[4][4], bh[4][2], bl[4][2];
#pragma unroll
            for (int i = 0; i < 4; i++) {
                uint32_t ad = a_addr0 + (uint32_t)(i * 16 * 80) + (uint32_t)(ks * 32);
                ldsm4(ah[i], ad);
                ldsm4(al[i], ad + 10240);
            }
#pragma unroll
            for (int p = 0; p < 2; p++) {
                uint32_t bd = b_addr0 + (uint32_t)(p * 16 * 80) + (uint32_t)(ks * 32);
                uint32_t tmp[4];
                ldsm4(tmp, bd);
                bh[p * 2 + 0][0] = tmp[0]; bh[p * 2 + 0][1] = tmp[1];
                bh[p * 2 + 1][0] = tmp[2]; bh[p * 2 + 1][1] = tmp[3];
                ldsm4(tmp, bd + 10240);
                bl[p * 2 + 0][0] = tmp[0]; bl[p * 2 + 0][1] = tmp[1];
                bl[p * 2 + 1][0] = tmp[2]; bl[p * 2 + 1][1] = tmp[3];
            }
#pragma unroll
            for (int i = 0; i < 4; i++)
#pragma unroll
                for (int j = 0; j < 4; j++)
                    mma16816(acc[i][j], ah[i], bh[j]);
#pragma unroll
            for (int i = 0; i < 4; i++)
#pragma unroll
                for (int j = 0; j < 4; j++)
                    mma16816(acc[i][j], ah[i], bl[j]);
#pragma unroll
            for (int i = 0; i < 4; i++)
#pragma unroll
                for (int j = 0; j < 4; j++)
                    mma16816(acc[i][j], al[i], bh[j]);
        }
        __syncthreads();
    }

    // epilogue (optional row remap through selmap)
#pragma unroll
    for (int i = 0; i < 4; i++) {
        int r0 = row0 + wm * 64 + i * 16 + (lane >> 2);
        int r1 = r0 + 8;
        size_t g0 = 0, g1 = 0;
        bool v0 = r0 < M, v1 = r1 < M;
        if (selmap) {
            if (v0) g0 = (size_t)((r0 / SELN) * N_ + selmap[r0]) * D_;
            if (v1) g1 = (size_t)((r1 / SELN) * N_ + selmap[r1]) * D_;
        } else {
            g0 = (size_t)r0 * D_;
            g1 = (size_t)r1 * D_;
        }
#pragma unroll
        for (int j = 0; j < 4; j++) {
            int col = col0 + wn * 32 + j * 8 + (lane & 3) * 2;
            float b0 = 0.f, b1 = 0.f;
            if (bias) { b0 = bias[col]; b1 = bias[col + 1]; }
            if (v0) {
                float2 o; o.x = acc[i][j][0] + b0; o.y = acc[i][j][1] + b1;
                *(float2*)(C + g0 + col) = o;
            }
            if (v1) {
                float2 o; o.x = acc[i][j][2] + b0; o.y = acc[i][j][3] + b1;
                *(float2*)(C + g1 + col) = o;
            }
        }
    }
}

// ---------------- attention: one block per (b, h), 58 queries ----------------
#define ATTN_SMEM_FLOATS (N_ * 64 + 64 * 64 + 64 + 64 + 256)
#define ATTN_SMEM_BYTES  (ATTN_SMEM_FLOATS * 4)

__global__ __launch_bounds__(256) void attn_kernel(
    const float* __restrict__ qsel, const float* __restrict__ kall,
    const float* __restrict__ vall,
    __nv_bfloat16* __restrict__ lhi, __nv_bfloat16* __restrict__ llo)
{
    extern __shared__ float sm[];
    float* P    = sm;                   // [577][64]
    float* Ks   = P + N_ * 64;          // [64][64]
    float* mx   = Ks + 64 * 64;         // [64]
    float* sums = mx + 64;              // [64]
    float* red  = sums + 64;            // [4][64]

    int bh = blockIdx.x;
    int h = bh % H_;
    int b = bh / H_;
    int t = threadIdx.x;
    int j = t & 63;
    int g = t >> 6;

    float4 q4[16];
    if (j < SELN) {
        const float4* qr = (const float4*)(qsel + ((size_t)(b * SELN + j)) * D_ + h * HD_);
#pragma unroll
        for (int i = 0; i < 16; i++) q4[i] = qr[i];
    } else {
#pragma unroll
        for (int i = 0; i < 16; i++) q4[i] = make_float4(0.f, 0.f, 0.f, 0.f);
    }

    // scores
    for (int n0 = 0; n0 < N_; n0 += 64) {
        int nend = min(64, N_ - n0);
        __syncthreads();
        for (int idx = t; idx < nend * 16; idx += 256) {
            int r = idx >> 4, cc = idx & 15;
            ((float4*)Ks)[r * 16 + cc] =
                *(const float4*)(kall + ((size_t)(b * N_ + n0 + r)) * D_ + h * HD_ + cc * 4);
        }
        __syncthreads();
#pragma unroll
        for (int i = 0; i < 16; i++) {
            int n = g * 16 + i;
            if (n < nend) {
                const float4* kr = (const float4*)(Ks + n * 64);
                float s = 0.f;
#pragma unroll
                for (int d = 0; d < 16; d++) {
                    float4 k = kr[d];
                    s += q4[d].x * k.x + q4[d].y * k.y + q4[d].z * k.z + q4[d].w * k.w;
                }
                P[(n0 + n) * 64 + j] = s * 0.125f;
            }
        }
    }
    __syncthreads();

    // softmax over keys per query j
    float m = -CUDART_INF_F;
    for (int n = g; n < N_; n += 4) m = fmaxf(m, P[n * 64 + j]);
    red[g * 64 + j] = m;
    __syncthreads();
    if (g == 0) mx[j] = fmaxf(fmaxf(red[j], red[64 + j]), fmaxf(red[128 + j], red[192 + j]));
    __syncthreads();
    float mm = mx[j];
    float ssum = 0.f;
    for (int n = g; n < N_; n += 4) {
        float e = __expf(P[n * 64 + j] - mm);
        P[n * 64 + j] = e;
        ssum += e;
    }
    red[g * 64 + j] = ssum;
    __syncthreads();
    if (g == 0) sums[j] = red[j] + red[64 + j] + red[128 + j] + red[192 + j];
    __syncthreads();
    float inv = 1.f / sums[j];

    // O = P @ V
    float4 o0 = make_float4(0.f, 0.f, 0.f, 0.f), o1 = o0, o2 = o0, o3 = o0;
    for (int n0 = 0; n0 < N_; n0 += 64) {
        int nend = min(64, N_ - n0);
        __syncthreads();
        for (int idx = t; idx < nend * 16; idx += 256) {
            int r = idx >> 4, cc = idx & 15;
            ((float4*)Ks)[r * 16 + cc] =
                *(const float4*)(vall + ((size_t)(b * N_ + n0 + r)) * D_ + h * HD_ + cc * 4);
        }
        __syncthreads();
        for (int n = 0; n < nend; n++) {
            float p = P[(n0 + n) * 64 + j];
            const float4* vr = (const float4*)(Ks + n * 64 + g * 16);
            float4 v0 = vr[0], v1 = vr[1], v2 = vr[2], v3 = vr[3];
            o0.x += p * v0.x; o0.y += p * v0.y; o0.z += p * v0.z; o0.w += p * v0.w;
            o1.x += p * v1.x; o1.y += p * v1.y; o1.z += p * v1.z; o1.w += p * v1.w;
            o2.x += p * v2.x; o2.y += p * v2.y; o2.z += p * v2.z; o2.w += p * v2.w;
            o3.x += p * v3.x; o3.y += p * v3.y; o3.z += p * v3.z; o3.w += p * v3.w;
        }
    }

    if (j < SELN) {
        size_t base = ((size_t)(b * SELN + j)) * D_ + h * HD_ + g * 16;
        float vals[16];
        vals[0] = o0.x * inv; vals[1] = o0.y * inv; vals[2] = o0.z * inv; vals[3] = o0.w * inv;
        vals[4] = o1.x * inv; vals[5] = o1.y * inv; vals[6] = o1.z * inv; vals[7] = o1.w * inv;
        vals[8] = o2.x * inv; vals[9] = o2.y * inv; vals[10] = o2.z * inv; vals[11] = o2.w * inv;
        vals[12] = o3.x * inv; vals[13] = o3.y * inv; vals[14] = o3.z * inv; vals[15] = o3.w * inv;
        uint32_t* ph = (uint32_t*)(lhi + base);
        uint32_t* pl = (uint32_t*)(llo + base);
#pragma unroll
        for (int p2 = 0; p2 < 8; p2++) {
            float a = vals[2 * p2], bv = vals[2 * p2 + 1];
            __nv_bfloat16 ha = __float2bfloat16(a), hb = __float2bfloat16(bv);
            __nv_bfloat16 la = __float2bfloat16(a - __bfloat162float(ha));
            __nv_bfloat16 lb = __float2bfloat16(bv - __bfloat162float(hb));
            ph[p2] = pack_bf16(ha, hb);
            pl[p2] = pack_bf16(la, lb);
        }
    }
}

// ---------------- host launcher ----------------
extern "C" void kernel_launch(void* const* d_in, const int* in_sizes, int n_in,
                              void* d_out, int out_size) {
    const float* x      = (const float*)d_in[0];
    const float* accatt = (const float*)d_in[1];
    const float* q_w    = (const float*)d_in[2];
    const float* k_w    = (const float*)d_in[3];
    const float* v_w    = (const float*)d_in[4];
    const float* proj_w = (const float*)d_in[5];
    const float* proj_b = (const float*)d_in[6];
    float* out = (float*)d_out;

    int* sel; cudaGetSymbolAddress((void**)&sel, g_sel);
    __nv_bfloat16 *xhi, *xlo, *xselhi, *xsello;
    __nv_bfloat16 *kwh, *kwl, *vwh, *vwl, *qwh, *qwl, *pwh, *pwl;
    float *qsel, *kall, *vall;
    cudaGetSymbolAddress((void**)&xhi, g_xhi);   cudaGetSymbolAddress((void**)&xlo, g_xlo);
    cudaGetSymbolAddress((void**)&xselhi, g_xselhi); cudaGetSymbolAddress((void**)&xsello, g_xsello);
    cudaGetSymbolAddress((void**)&kwh, g_kwh);   cudaGetSymbolAddress((void**)&kwl, g_kwl);
    cudaGetSymbolAddress((void**)&vwh, g_vwh);   cudaGetSymbolAddress((void**)&vwl, g_vwl);
    cudaGetSymbolAddress((void**)&qwh, g_qwh);   cudaGetSymbolAddress((void**)&qwl, g_qwl);
    cudaGetSymbolAddress((void**)&pwh, g_pwh);   cudaGetSymbolAddress((void**)&pwl, g_pwl);
    cudaGetSymbolAddress((void**)&qsel, g_qsel);
    cudaGetSymbolAddress((void**)&kall, g_kall); cudaGetSymbolAddress((void**)&vall, g_vall);

    cudaFuncSetAttribute(gemm_kernel, cudaFuncAttributeMaxDynamicSharedMemorySize, GSMEM);
    cudaFuncSetAttribute(attn_kernel, cudaFuncAttributeMaxDynamicSharedMemorySize, ATTN_SMEM_BYTES);

    const int NX4 = M_ALL * D_ / 4;

    // launches 1-5: splits (x first; weights merged into one big + one leftover q)
    split_kernel<<<4096, 256>>>((const float4*)x, (uint2*)xhi, (uint2*)xlo, NX4);
    split_w_kernel<<<2048, 256>>>((const float4*)k_w, (uint2*)kwh, (uint2*)kwl,
                                  (const float4*)v_w, (uint2*)vwh, (uint2*)vwl,
                                  (const float4*)proj_w, (uint2*)pwh, (uint2*)pwl,
                                  (const float4*)q_w, (uint2*)qwh, (uint2*)qwl);
    topk_kernel<<<B_, 256>>>(accatt, sel);
    gather_kernel<<<M_SEL, 128>>>(xhi, xlo, sel, xselhi, xsello);
    // launch 5 (index 4): Q projection for selected rows
    Seg sq = { qwh, qwl, qsel, nullptr };
    gemm_kernel<<<dim3(6, 29), 256, GSMEM>>>(xselhi, xsello, sq, sq, sq, M_SEL, 6, nullptr);

    // launch 6 (index 5, ncu -s 5 -c 1 profiles this): fused K | V | proj GEMM
    Seg sk = { kwh, kwl, kall, nullptr };
    Seg sv = { vwh, vwl, vall, nullptr };
    Seg sp = { pwh, pwl, out,  proj_b };
    gemm_kernel<<<dim3(18, 289), 256, GSMEM>>>(xhi, xlo, sk, sv, sp, M_ALL, 6, nullptr);

    // attention -> local_out (split bf16) into xselhi/xsello (Q gemm already consumed them)
    attn_kernel<<<B_ * H_, 256, ATTN_SMEM_BYTES>>>(qsel, kall, vall, xselhi, xsello);

    // correction: overwrite selected rows of out with local_out @ proj^T + bias
    Seg sc = { pwh, pwl, out, proj_b };
    gemm_kernel<<<dim3(6, 29), 256, GSMEM>>>(xselhi, xsello, sc, sc, sc, M_SEL, 6, sel);
}

// round 5
// speedup vs baseline: 2.5162x; 1.0447x over previous
#include <cuda_runtime.h>
#include <cuda_bf16.h>
#include <cstdint>
#include <math_constants.h>

// ---------------- problem constants ----------------
#define B_   64
#define N_   577
#define D_   768
#define H_   12
#define HD_  64
#define KK_  57
#define SELN 58
#define M_ALL (B_ * N_)    // 36928
#define M_SEL (B_ * SELN)  // 3712

// ---------------- scratch ----------------
__device__ int   g_sel[M_SEL];
__device__ float g_xsel[(size_t)M_SEL * D_];
__device__ float g_qsel[(size_t)M_SEL * D_];
__device__ float g_lout[(size_t)M_SEL * D_];
__device__ float g_kall[(size_t)M_ALL * D_];
__device__ float g_vall[(size_t)M_ALL * D_];

// ---------------- helpers ----------------
__device__ __forceinline__ uint32_t smem_u32(const void* p) {
    uint32_t a;
    asm("{ .reg .u64 t; cvta.to.shared.u64 t, %1; cvt.u32.u64 %0, t; }" : "=r"(a) : "l"(p));
    return a;
}
__device__ __forceinline__ void cp16(uint32_t dst, const void* src, uint32_t sz) {
    asm volatile("cp.async.cg.shared.global [%0], [%1], 16, %2;" :: "r"(dst), "l"(src), "r"(sz) : "memory");
}
#define CP_COMMIT() asm volatile("cp.async.commit_group;" ::: "memory")
#define CP_WAIT0()  asm volatile("cp.async.wait_group 0;" ::: "memory")
#define CP_WAIT1()  asm volatile("cp.async.wait_group 1;" ::: "memory")

__device__ __forceinline__ uint32_t f2tf32(float f) {
    uint32_t u;
    asm("cvt.rna.tf32.f32 %0, %1;" : "=r"(u) : "f"(f));
    return u;
}
__device__ __forceinline__ void mma_tf32(float* d, const uint32_t* a, const uint32_t* b) {
    asm volatile(
        "mma.sync.aligned.m16n8k8.row.col.f32.tf32.tf32.f32 "
        "{%0,%1,%2,%3}, {%4,%5,%6,%7}, {%8,%9}, {%0,%1,%2,%3};"
        : "+f"(d[0]), "+f"(d[1]), "+f"(d[2]), "+f"(d[3])
        : "r"(a[0]), "r"(a[1]), "r"(a[2]), "r"(a[3]), "r"(b[0]), "r"(b[1]));
}

// ---------------- top-k (iterative argmax, one block per batch) ----------------
__global__ void topk_kernel(const float* __restrict__ acc, int* __restrict__ sel) {
    int b = blockIdx.x;
    __shared__ float vals[N_ - 1];
    __shared__ float rv[256];
    __shared__ int   ri[256];
    int t = threadIdx.x;
    const float* src = acc + (size_t)b * N_ * N_ + 1;
    for (int i = t; i < N_ - 1; i += 256) vals[i] = src[i];
    if (t == 0) sel[b * SELN] = 0;
    __syncthreads();
    for (int it = 0; it < KK_; it++) {
        float best = -CUDART_INF_F; int bi = 0;
        for (int i = t; i < N_ - 1; i += 256) {
            float v = vals[i];
            if (v > best) { best = v; bi = i; }
        }
        rv[t] = best; ri[t] = bi;
        __syncthreads();
        for (int s = 128; s > 0; s >>= 1) {
            if (t < s && rv[t + s] > rv[t]) { rv[t] = rv[t + s]; ri[t] = ri[t + s]; }
            __syncthreads();
        }
        if (t == 0) { sel[b * SELN + 1 + it] = ri[0] + 1; vals[ri[0]] = -CUDART_INF_F; }
        __syncthreads();
    }
}

// ---------------- gather selected fp32 rows of x ----------------
__global__ void gather_kernel(const float* __restrict__ x, const int* __restrict__ sel,
                              float* __restrict__ dst) {
    int m = blockIdx.x;
    int b = m / SELN;
    int tok = sel[m];
    const float4* s = (const float4*)(x + ((size_t)(b * N_ + tok)) * D_);
    float4* d = (float4*)(dst + (size_t)m * D_);
    int i = threadIdx.x;
    d[i] = s[i];
}

// ---------------- TF32 HMMA GEMM ----------------
// Segmented along grid.x. C[m, col0+c] = sum_k A[m,k]*B[col0+c,k] (+bias).
// BM=128 BN=128 BK=32, 256 threads = 8 warps (2 m x 4 n), warp tile 64x32.
// smem tile: 128 rows x 36 floats (32 data + 4 pad) = 18432 B per operand.
// If selmap != null, output row m remaps to (m/SELN)*N_ + selmap[m].
struct Seg {
    const float* bw;
    float* c;
    const float* bias;
};
#define TSTRIDE 36
#define TILE_B  (128 * TSTRIDE * 4)     // 18432
#define STG     (2 * TILE_B)            // 36864
#define GSMEM   (2 * STG)               // 73728
#define KITERS  (D_ / 32)               // 24

__global__ __launch_bounds__(256) void gemm_kernel(
    const float* __restrict__ A,
    Seg s0, Seg s1, Seg s2,
    int M, int per, const int* __restrict__ selmap)
{
    extern __shared__ char smem[];
    uint32_t sb = smem_u32(smem);
    int tid = threadIdx.x;
    int lane = tid & 31;
    int wid = tid >> 5;
    int wm = wid & 1, wn = wid >> 1;
    int gid = lane >> 2, tig = lane & 3;
    int bx = blockIdx.x, by = blockIdx.y;

    int seg = bx / per;
    Seg S = (seg == 0) ? s0 : (seg == 1) ? s1 : s2;
    int nb = bx - seg * per;
    const float* Bw = S.bw;
    float* C = S.c;
    const float* bias = S.bias;
    int col0 = nb * 128;
    int row0 = by * 128;

    float acc[4][4][4];
#pragma unroll
    for (int i = 0; i < 4; i++)
#pragma unroll
        for (int j = 0; j < 4; j++)
#pragma unroll
            for (int r = 0; r < 4; r++) acc[i][j][r] = 0.f;

    auto load_stage = [&](int buf, int k0) {
        uint32_t base = sb + buf * STG;
#pragma unroll
        for (int q = 0; q < 4; q++) {
            int idx = tid + q * 256;            // 0..1023
            int r = idx >> 3, c8 = idx & 7;     // row, 16B chunk
            int gm = row0 + r;
            uint32_t sz = (gm < M) ? 16u : 0u;
            int cg = gm < M ? gm : (M - 1);
            cp16(base + r * 144 + c8 * 16, A + (size_t)cg * D_ + k0 + c8 * 4, sz);
            cp16(base + TILE_B + r * 144 + c8 * 16,
                 Bw + (size_t)(col0 + r) * D_ + k0 + c8 * 4, 16u);
        }
    };

    load_stage(0, 0);
    CP_COMMIT();

    for (int it = 0; it < KITERS; it++) {
        int buf = it & 1;
        if (it + 1 < KITERS) {
            load_stage(buf ^ 1, (it + 1) * 32);
            CP_COMMIT();
            CP_WAIT1();
        } else {
            CP_WAIT0();
        }
        __syncthreads();

        const float* As = (const float*)(smem + buf * STG);
        const float* Bs = (const float*)(smem + buf * STG + TILE_B);
        int arow = wm * 64 + gid;
        int brow = wn * 32 + gid;

#pragma unroll
        for (int ks = 0; ks < 4; ks++) {
            int c0 = ks * 8 + tig;
            uint32_t af[4][4], bf[4][2];
#pragma unroll
            for (int i = 0; i < 4; i++) {
                const float* ap = As + (arow + i * 16) * TSTRIDE;
                af[i][0] = f2tf32(ap[c0]);
                af[i][1] = f2tf32(ap[8 * TSTRIDE + c0]);
                af[i][2] = f2tf32(ap[c0 + 4]);
                af[i][3] = f2tf32(ap[8 * TSTRIDE + c0 + 4]);
            }
#pragma unroll
            for (int j = 0; j < 4; j++) {
                const float* bp = Bs + (brow + j * 8) * TSTRIDE;
                bf[j][0] = f2tf32(bp[c0]);
                bf[j][1] = f2tf32(bp[c0 + 4]);
            }
#pragma unroll
            for (int i = 0; i < 4; i++)
#pragma unroll
                for (int j = 0; j < 4; j++)
                    mma_tf32(acc[i][j], af[i], bf[j]);
        }
        __syncthreads();
    }

    // epilogue (optional row remap through selmap)
#pragma unroll
    for (int i = 0; i < 4; i++) {
        int r0 = row0 + wm * 64 + i * 16 + gid;
        int r1 = r0 + 8;
        size_t g0 = 0, g1 = 0;
        bool v0 = r0 < M, v1 = r1 < M;
        if (selmap) {
            if (v0) g0 = (size_t)((r0 / SELN) * N_ + selmap[r0]) * D_;
            if (v1) g1 = (size_t)((r1 / SELN) * N_ + selmap[r1]) * D_;
        } else {
            g0 = (size_t)r0 * D_;
            g1 = (size_t)r1 * D_;
        }
#pragma unroll
        for (int j = 0; j < 4; j++) {
            int col = col0 + wn * 32 + j * 8 + tig * 2;
            float b0 = 0.f, b1 = 0.f;
            if (bias) { b0 = bias[col]; b1 = bias[col + 1]; }
            if (v0) {
                float2 o; o.x = acc[i][j][0] + b0; o.y = acc[i][j][1] + b1;
                *(float2*)(C + g0 + col) = o;
            }
            if (v1) {
                float2 o; o.x = acc[i][j][2] + b0; o.y = acc[i][j][3] + b1;
                *(float2*)(C + g1 + col) = o;
            }
        }
    }
}

// ---------------- attention: one block per (b, h), 58 queries ----------------
#define ATTN_SMEM_FLOATS (N_ * 64 + 64 * 64 + 64 + 64 + 256)
#define ATTN_SMEM_BYTES  (ATTN_SMEM_FLOATS * 4)

__global__ __launch_bounds__(256) void attn_kernel(
    const float* __restrict__ qsel, const float* __restrict__ kall,
    const float* __restrict__ vall, float* __restrict__ lout)
{
    extern __shared__ float sm[];
    float* P    = sm;                   // [577][64]
    float* Ks   = P + N_ * 64;          // [64][64]
    float* mx   = Ks + 64 * 64;         // [64]
    float* sums = mx + 64;              // [64]
    float* red  = sums + 64;            // [4][64]

    int bh = blockIdx.x;
    int h = bh % H_;
    int b = bh / H_;
    int t = threadIdx.x;
    int j = t & 63;
    int g = t >> 6;

    float4 q4[16];
    if (j < SELN) {
        const float4* qr = (const float4*)(qsel + ((size_t)(b * SELN + j)) * D_ + h * HD_);
#pragma unroll
        for (int i = 0; i < 16; i++) q4[i] = qr[i];
    } else {
#pragma unroll
        for (int i = 0; i < 16; i++) q4[i] = make_float4(0.f, 0.f, 0.f, 0.f);
    }

    // scores
    for (int n0 = 0; n0 < N_; n0 += 64) {
        int nend = min(64, N_ - n0);
        __syncthreads();
        for (int idx = t; idx < nend * 16; idx += 256) {
            int r = idx >> 4, cc = idx & 15;
            ((float4*)Ks)[r * 16 + cc] =
                *(const float4*)(kall + ((size_t)(b * N_ + n0 + r)) * D_ + h * HD_ + cc * 4);
        }
        __syncthreads();
#pragma unroll
        for (int i = 0; i < 16; i++) {
            int n = g * 16 + i;
            if (n < nend) {
                const float4* kr = (const float4*)(Ks + n * 64);
                float s = 0.f;
#pragma unroll
                for (int d = 0; d < 16; d++) {
                    float4 k = kr[d];
                    s += q4[d].x * k.x + q4[d].y * k.y + q4[d].z * k.z + q4[d].w * k.w;
                }
                P[(n0 + n) * 64 + j] = s * 0.125f;
            }
        }
    }
    __syncthreads();

    // softmax over keys per query j
    float m = -CUDART_INF_F;
    for (int n = g; n < N_; n += 4) m = fmaxf(m, P[n * 64 + j]);
    red[g * 64 + j] = m;
    __syncthreads();
    if (g == 0) mx[j] = fmaxf(fmaxf(red[j], red[64 + j]), fmaxf(red[128 + j], red[192 + j]));
    __syncthreads();
    float mm = mx[j];
    float ssum = 0.f;
    for (int n = g; n < N_; n += 4) {
        float e = __expf(P[n * 64 + j] - mm);
        P[n * 64 + j] = e;
        ssum += e;
    }
    red[g * 64 + j] = ssum;
    __syncthreads();
    if (g == 0) sums[j] = red[j] + red[64 + j] + red[128 + j] + red[192 + j];
    __syncthreads();
    float inv = 1.f / sums[j];

    // O = P @ V
    float4 o0 = make_float4(0.f, 0.f, 0.f, 0.f), o1 = o0, o2 = o0, o3 = o0;
    for (int n0 = 0; n0 < N_; n0 += 64) {
        int nend = min(64, N_ - n0);
        __syncthreads();
        for (int idx = t; idx < nend * 16; idx += 256) {
            int r = idx >> 4, cc = idx & 15;
            ((float4*)Ks)[r * 16 + cc] =
                *(const float4*)(vall + ((size_t)(b * N_ + n0 + r)) * D_ + h * HD_ + cc * 4);
        }
        __syncthreads();
        for (int n = 0; n < nend; n++) {
            float p = P[(n0 + n) * 64 + j];
            const float4* vr = (const float4*)(Ks + n * 64 + g * 16);
            float4 v0 = vr[0], v1 = vr[1], v2 = vr[2], v3 = vr[3];
            o0.x += p * v0.x; o0.y += p * v0.y; o0.z += p * v0.z; o0.w += p * v0.w;
            o1.x += p * v1.x; o1.y += p * v1.y; o1.z += p * v1.z; o1.w += p * v1.w;
            o2.x += p * v2.x; o2.y += p * v2.y; o2.z += p * v2.z; o2.w += p * v2.w;
            o3.x += p * v3.x; o3.y += p * v3.y; o3.z += p * v3.z; o3.w += p * v3.w;
        }
    }

    if (j < SELN) {
        float4* dst = (float4*)(lout + ((size_t)(b * SELN + j)) * D_ + h * HD_ + g * 16);
        float4 w0, w1, w2, w3;
        w0.x = o0.x * inv; w0.y = o0.y * inv; w0.z = o0.z * inv; w0.w = o0.w * inv;
        w1.x = o1.x * inv; w1.y = o1.y * inv; w1.z = o1.z * inv; w1.w = o1.w * inv;
        w2.x = o2.x * inv; w2.y = o2.y * inv; w2.z = o2.z * inv; w2.w = o2.w * inv;
        w3.x = o3.x * inv; w3.y = o3.y * inv; w3.z = o3.z * inv; w3.w = o3.w * inv;
        dst[0] = w0; dst[1] = w1; dst[2] = w2; dst[3] = w3;
    }
}

// ---------------- host launcher ----------------
extern "C" void kernel_launch(void* const* d_in, const int* in_sizes, int n_in,
                              void* d_out, int out_size) {
    const float* x      = (const float*)d_in[0];
    const float* accatt = (const float*)d_in[1];
    const float* q_w    = (const float*)d_in[2];
    const float* k_w    = (const float*)d_in[3];
    const float* v_w    = (const float*)d_in[4];
    const float* proj_w = (const float*)d_in[5];
    const float* proj_b = (const float*)d_in[6];
    float* out = (float*)d_out;

    int* sel; cudaGetSymbolAddress((void**)&sel, g_sel);
    float *xsel, *qsel, *lout, *kall, *vall;
    cudaGetSymbolAddress((void**)&xsel, g_xsel);
    cudaGetSymbolAddress((void**)&qsel, g_qsel);
    cudaGetSymbolAddress((void**)&lout, g_lout);
    cudaGetSymbolAddress((void**)&kall, g_kall);
    cudaGetSymbolAddress((void**)&vall, g_vall);

    cudaFuncSetAttribute(gemm_kernel, cudaFuncAttributeMaxDynamicSharedMemorySize, GSMEM);
    cudaFuncSetAttribute(attn_kernel, cudaFuncAttributeMaxDynamicSharedMemorySize, ATTN_SMEM_BYTES);

    // selection + gather
    topk_kernel<<<B_, 256>>>(accatt, sel);
    gather_kernel<<<M_SEL, 192>>>(x, sel, xsel);

    // Q projection for selected rows
    Seg sq = { q_w, qsel, nullptr };
    gemm_kernel<<<dim3(6, 29), 256, GSMEM>>>(xsel, sq, sq, sq, M_SEL, 6, nullptr);

    // fused K | V | proj GEMM over all rows
    Seg sk = { k_w, kall, nullptr };
    Seg sv = { v_w, vall, nullptr };
    Seg sp = { proj_w, out, proj_b };
    gemm_kernel<<<dim3(18, 289), 256, GSMEM>>>(x, sk, sv, sp, M_ALL, 6, nullptr);

    // attention over selected queries -> lout (fp32)
    attn_kernel<<<B_ * H_, 256, ATTN_SMEM_BYTES>>>(qsel, kall, vall, lout);

    // correction: overwrite selected rows of out with lout @ proj^T + bias
    Seg sc = { proj_w, out, proj_b };
    gemm_kernel<<<dim3(6, 29), 256, GSMEM>>>(lout, sc, sc, sc, M_SEL, 6, sel);
}

// round 6
// speedup vs baseline: 2.8455x; 1.1309x over previous
#include <cuda_runtime.h>
#include <cuda_bf16.h>
#include <cstdint>
#include <math_constants.h>

// ---------------- problem constants ----------------
#define B_   64
#define N_   577
#define D_   768
#define H_   12
#define HD_  64
#define KK_  57
#define SELN 58
#define M_ALL (B_ * N_)    // 36928
#define M_SEL (B_ * SELN)  // 3712

// ---------------- scratch ----------------
__device__ int   g_sel[M_SEL];
__device__ float g_xt[(size_t)M_ALL * D_];       // tf32-rounded x
__device__ float g_wq[D_ * D_], g_wk[D_ * D_], g_wv[D_ * D_], g_wp[D_ * D_];
__device__ float g_xsel[(size_t)M_SEL * D_];
__device__ float g_qsel[(size_t)M_SEL * D_];
__device__ float g_lout[(size_t)M_SEL * D_];
__device__ float g_kall[(size_t)M_ALL * D_];
__device__ float g_vall[(size_t)M_ALL * D_];

// ---------------- helpers ----------------
__device__ __forceinline__ uint32_t smem_u32(const void* p) {
    uint32_t a;
    asm("{ .reg .u64 t; cvta.to.shared.u64 t, %1; cvt.u32.u64 %0, t; }" : "=r"(a) : "l"(p));
    return a;
}
__device__ __forceinline__ void cp16(uint32_t dst, const void* src, uint32_t sz) {
    asm volatile("cp.async.cg.shared.global [%0], [%1], 16, %2;" :: "r"(dst), "l"(src), "r"(sz) : "memory");
}
#define CP_COMMIT() asm volatile("cp.async.commit_group;" ::: "memory")
#define CP_WAIT0()  asm volatile("cp.async.wait_group 0;" ::: "memory")
#define CP_WAIT1()  asm volatile("cp.async.wait_group 1;" ::: "memory")

__device__ __forceinline__ uint32_t f2tf32(float f) {
    uint32_t u;
    asm("cvt.rna.tf32.f32 %0, %1;" : "=r"(u) : "f"(f));
    return u;
}
__device__ __forceinline__ void mma_tf32(float* d, const uint32_t* a, const uint32_t* b) {
    asm volatile(
        "mma.sync.aligned.m16n8k8.row.col.f32.tf32.tf32.f32 "
        "{%0,%1,%2,%3}, {%4,%5,%6,%7}, {%8,%9}, {%0,%1,%2,%3};"
        : "+f"(d[0]), "+f"(d[1]), "+f"(d[2]), "+f"(d[3])
        : "r"(a[0]), "r"(a[1]), "r"(a[2]), "r"(a[3]), "r"(b[0]), "r"(b[1]));
}

// ---------------- tf32 pre-round: dst = rna(src) ----------------
__global__ void round_kernel(const float4* __restrict__ src, uint4* __restrict__ dst, int n4) {
    int i = blockIdx.x * blockDim.x + threadIdx.x;
    int stride = gridDim.x * blockDim.x;
    for (; i < n4; i += stride) {
        float4 v = src[i];
        uint4 o;
        o.x = f2tf32(v.x); o.y = f2tf32(v.y); o.z = f2tf32(v.z); o.w = f2tf32(v.w);
        dst[i] = o;
    }
}
// 4 weights in one launch, segmented by blockIdx.x
__global__ void round_w4_kernel(const float4* w0, uint4* d0, const float4* w1, uint4* d1,
                                const float4* w2, uint4* d2, const float4* w3, uint4* d3) {
    int s = blockIdx.x >> 9;
    int local = blockIdx.x & 511;
    const float4* src = s == 0 ? w0 : s == 1 ? w1 : s == 2 ? w2 : w3;
    uint4* dst = s == 0 ? d0 : s == 1 ? d1 : s == 2 ? d2 : d3;
    const int n4 = D_ * D_ / 4;
    for (int i = local * 256 + threadIdx.x; i < n4; i += 512 * 256) {
        float4 v = src[i];
        uint4 o;
        o.x = f2tf32(v.x); o.y = f2tf32(v.y); o.z = f2tf32(v.z); o.w = f2tf32(v.w);
        dst[i] = o;
    }
}

// ---------------- top-k (iterative argmax, one block per batch) ----------------
__global__ void topk_kernel(const float* __restrict__ acc, int* __restrict__ sel) {
    int b = blockIdx.x;
    __shared__ float vals[N_ - 1];
    __shared__ float rv[256];
    __shared__ int   ri[256];
    int t = threadIdx.x;
    const float* src = acc + (size_t)b * N_ * N_ + 1;
    for (int i = t; i < N_ - 1; i += 256) vals[i] = src[i];
    if (t == 0) sel[b * SELN] = 0;
    __syncthreads();
    for (int it = 0; it < KK_; it++) {
        float best = -CUDART_INF_F; int bi = 0;
        for (int i = t; i < N_ - 1; i += 256) {
            float v = vals[i];
            if (v > best) { best = v; bi = i; }
        }
        rv[t] = best; ri[t] = bi;
        __syncthreads();
        for (int s = 128; s > 0; s >>= 1) {
            if (t < s && rv[t + s] > rv[t]) { rv[t] = rv[t + s]; ri[t] = ri[t + s]; }
            __syncthreads();
        }
        if (t == 0) { sel[b * SELN + 1 + it] = ri[0] + 1; vals[ri[0]] = -CUDART_INF_F; }
        __syncthreads();
    }
}

// ---------------- gather selected rows of xt ----------------
__global__ void gather_kernel(const float* __restrict__ x, const int* __restrict__ sel,
                              float* __restrict__ dst) {
    int m = blockIdx.x;
    int b = m / SELN;
    int tok = sel[m];
    const float4* s = (const float4*)(x + ((size_t)(b * N_ + tok)) * D_);
    float4* d = (float4*)(dst + (size_t)m * D_);
    int i = threadIdx.x;
    d[i] = s[i];
}

// ---------------- TF32 HMMA GEMM (inputs pre-rounded to tf32) ----------------
// Segmented along grid.x. C[m, col0+c] = sum_k A[m,k]*B[col0+c,k] (+bias).
// BM=128 BN=128 BK=32, 256 threads = 8 warps (2 m x 4 n), warp tile 64x32.
// smem tile: 128 rows x 36 floats (32 data + 4 pad) per operand.
// If selmap != null, output row m remaps to (m/SELN)*N_ + selmap[m].
struct Seg {
    const float* bw;
    float* c;
    const float* bias;
};
#define TSTRIDE 36
#define TILE_B  (128 * TSTRIDE * 4)     // 18432
#define STG     (2 * TILE_B)            // 36864
#define GSMEM   (2 * STG)               // 73728
#define KITERS  (D_ / 32)               // 24

__global__ __launch_bounds__(256, 2) void gemm_kernel(
    const float* __restrict__ A,
    Seg s0, Seg s1, Seg s2,
    int M, int per, const int* __restrict__ selmap)
{
    extern __shared__ char smem[];
    uint32_t sb = smem_u32(smem);
    int tid = threadIdx.x;
    int lane = tid & 31;
    int wid = tid >> 5;
    int wm = wid & 1, wn = wid >> 1;
    int gid = lane >> 2, tig = lane & 3;
    int bx = blockIdx.x, by = blockIdx.y;

    int seg = bx / per;
    Seg S = (seg == 0) ? s0 : (seg == 1) ? s1 : s2;
    int nb = bx - seg * per;
    const float* Bw = S.bw;
    float* C = S.c;
    const float* bias = S.bias;
    int col0 = nb * 128;
    int row0 = by * 128;

    float acc[4][4][4];
#pragma unroll
    for (int i = 0; i < 4; i++)
#pragma unroll
        for (int j = 0; j < 4; j++)
#pragma unroll
            for (int r = 0; r < 4; r++) acc[i][j][r] = 0.f;

    auto load_stage = [&](int buf, int k0) {
        uint32_t base = sb + buf * STG;
#pragma unroll
        for (int q = 0; q < 4; q++) {
            int idx = tid + q * 256;            // 0..1023
            int r = idx >> 3, c8 = idx & 7;     // row, 16B chunk
            int gm = row0 + r;
            uint32_t sz = (gm < M) ? 16u : 0u;
            int cg = gm < M ? gm : (M - 1);
            cp16(base + r * 144 + c8 * 16, A + (size_t)cg * D_ + k0 + c8 * 4, sz);
            cp16(base + TILE_B + r * 144 + c8 * 16,
                 Bw + (size_t)(col0 + r) * D_ + k0 + c8 * 4, 16u);
        }
    };

    load_stage(0, 0);
    CP_COMMIT();

    for (int it = 0; it < KITERS; it++) {
        int buf = it & 1;
        if (it + 1 < KITERS) {
            load_stage(buf ^ 1, (it + 1) * 32);
            CP_COMMIT();
            CP_WAIT1();
        } else {
            CP_WAIT0();
        }
        __syncthreads();

        const uint32_t* As = (const uint32_t*)(smem + buf * STG);
        const uint32_t* Bs = (const uint32_t*)(smem + buf * STG + TILE_B);
        int arow = wm * 64 + gid;
        int brow = wn * 32 + gid;

#pragma unroll
        for (int ks = 0; ks < 4; ks++) {
            int c0 = ks * 8 + tig;
            uint32_t af[4][4], bf[4][2];
#pragma unroll
            for (int i = 0; i < 4; i++) {
                const uint32_t* ap = As + (arow + i * 16) * TSTRIDE;
                af[i][0] = ap[c0];
                af[i][1] = ap[8 * TSTRIDE + c0];
                af[i][2] = ap[c0 + 4];
                af[i][3] = ap[8 * TSTRIDE + c0 + 4];
            }
#pragma unroll
            for (int j = 0; j < 4; j++) {
                const uint32_t* bp = Bs + (brow + j * 8) * TSTRIDE;
                bf[j][0] = bp[c0];
                bf[j][1] = bp[c0 + 4];
            }
#pragma unroll
            for (int i = 0; i < 4; i++)
#pragma unroll
                for (int j = 0; j < 4; j++)
                    mma_tf32(acc[i][j], af[i], bf[j]);
        }
        __syncthreads();
    }

    // epilogue (optional row remap through selmap)
#pragma unroll
    for (int i = 0; i < 4; i++) {
        int r0 = row0 + wm * 64 + i * 16 + gid;
        int r1 = r0 + 8;
        size_t g0 = 0, g1 = 0;
        bool v0 = r0 < M, v1 = r1 < M;
        if (selmap) {
            if (v0) g0 = (size_t)((r0 / SELN) * N_ + selmap[r0]) * D_;
            if (v1) g1 = (size_t)((r1 / SELN) * N_ + selmap[r1]) * D_;
        } else {
            g0 = (size_t)r0 * D_;
            g1 = (size_t)r1 * D_;
        }
#pragma unroll
        for (int j = 0; j < 4; j++) {
            int col = col0 + wn * 32 + j * 8 + tig * 2;
            float b0 = 0.f, b1 = 0.f;
            if (bias) { b0 = bias[col]; b1 = bias[col + 1]; }
            if (v0) {
                float2 o; o.x = acc[i][j][0] + b0; o.y = acc[i][j][1] + b1;
                *(float2*)(C + g0 + col) = o;
            }
            if (v1) {
                float2 o; o.x = acc[i][j][2] + b0; o.y = acc[i][j][3] + b1;
                *(float2*)(C + g1 + col) = o;
            }
        }
    }
}

// ---------------- attention: one block per (b, h), 58 queries ----------------
#define ATTN_SMEM_FLOATS (N_ * 64 + 64 * 64 + 64 + 64 + 256)
#define ATTN_SMEM_BYTES  (ATTN_SMEM_FLOATS * 4)

__global__ __launch_bounds__(256) void attn_kernel(
    const float* __restrict__ qsel, const float* __restrict__ kall,
    const float* __restrict__ vall, float* __restrict__ lout)
{
    extern __shared__ float sm[];
    float* P    = sm;                   // [577][64]
    float* Ks   = P + N_ * 64;          // [64][64]
    float* mx   = Ks + 64 * 64;         // [64]
    float* sums = mx + 64;              // [64]
    float* red  = sums + 64;            // [4][64]

    int bh = blockIdx.x;
    int h = bh % H_;
    int b = bh / H_;
    int t = threadIdx.x;
    int j = t & 63;
    int g = t >> 6;

    float4 q4[16];
    if (j < SELN) {
        const float4* qr = (const float4*)(qsel + ((size_t)(b * SELN + j)) * D_ + h * HD_);
#pragma unroll
        for (int i = 0; i < 16; i++) q4[i] = qr[i];
    } else {
#pragma unroll
        for (int i = 0; i < 16; i++) q4[i] = make_float4(0.f, 0.f, 0.f, 0.f);
    }

    // scores
    for (int n0 = 0; n0 < N_; n0 += 64) {
        int nend = min(64, N_ - n0);
        __syncthreads();
        for (int idx = t; idx < nend * 16; idx += 256) {
            int r = idx >> 4, cc = idx & 15;
            ((float4*)Ks)[r * 16 + cc] =
                *(const float4*)(kall + ((size_t)(b * N_ + n0 + r)) * D_ + h * HD_ + cc * 4);
        }
        __syncthreads();
#pragma unroll
        for (int i = 0; i < 16; i++) {
            int n = g * 16 + i;
            if (n < nend) {
                const float4* kr = (const float4*)(Ks + n * 64);
                float s = 0.f;
#pragma unroll
                for (int d = 0; d < 16; d++) {
                    float4 k = kr[d];
                    s += q4[d].x * k.x + q4[d].y * k.y + q4[d].z * k.z + q4[d].w * k.w;
                }
                P[(n0 + n) * 64 + j] = s * 0.125f;
            }
        }
    }
    __syncthreads();

    // softmax over keys per query j
    float m = -CUDART_INF_F;
    for (int n = g; n < N_; n += 4) m = fmaxf(m, P[n * 64 + j]);
    red[g * 64 + j] = m;
    __syncthreads();
    if (g == 0) mx[j] = fmaxf(fmaxf(red[j], red[64 + j]), fmaxf(red[128 + j], red[192 + j]));
    __syncthreads();
    float mm = mx[j];
    float ssum = 0.f;
    for (int n = g; n < N_; n += 4) {
        float e = __expf(P[n * 64 + j] - mm);
        P[n * 64 + j] = e;
        ssum += e;
    }
    red[g * 64 + j] = ssum;
    __syncthreads();
    if (g == 0) sums[j] = red[j] + red[64 + j] + red[128 + j] + red[192 + j];
    __syncthreads();
    float inv = 1.f / sums[j];

    // O = P @ V
    float4 o0 = make_float4(0.f, 0.f, 0.f, 0.f), o1 = o0, o2 = o0, o3 = o0;
    for (int n0 = 0; n0 < N_; n0 += 64) {
        int nend = min(64, N_ - n0);
        __syncthreads();
        for (int idx = t; idx < nend * 16; idx += 256) {
            int r = idx >> 4, cc = idx & 15;
            ((float4*)Ks)[r * 16 + cc] =
                *(const float4*)(vall + ((size_t)(b * N_ + n0 + r)) * D_ + h * HD_ + cc * 4);
        }
        __syncthreads();
        for (int n = 0; n < nend; n++) {
            float p = P[(n0 + n) * 64 + j];
            const float4* vr = (const float4*)(Ks + n * 64 + g * 16);
            float4 v0 = vr[0], v1 = vr[1], v2 = vr[2], v3 = vr[3];
            o0.x += p * v0.x; o0.y += p * v0.y; o0.z += p * v0.z; o0.w += p * v0.w;
            o1.x += p * v1.x; o1.y += p * v1.y; o1.z += p * v1.z; o1.w += p * v1.w;
            o2.x += p * v2.x; o2.y += p * v2.y; o2.z += p * v2.z; o2.w += p * v2.w;
            o3.x += p * v3.x; o3.y += p * v3.y; o3.z += p * v3.z; o3.w += p * v3.w;
        }
    }

    if (j < SELN) {
        // tf32-round the attention output so the correction GEMM needs no cvt
        uint4* dst = (uint4*)(lout + ((size_t)(b * SELN + j)) * D_ + h * HD_ + g * 16);
        uint4 w0, w1, w2, w3;
        w0.x = f2tf32(o0.x * inv); w0.y = f2tf32(o0.y * inv); w0.z = f2tf32(o0.z * inv); w0.w = f2tf32(o0.w * inv);
        w1.x = f2tf32(o1.x * inv); w1.y = f2tf32(o1.y * inv); w1.z = f2tf32(o1.z * inv); w1.w = f2tf32(o1.w * inv);
        w2.x = f2tf32(o2.x * inv); w2.y = f2tf32(o2.y * inv); w2.z = f2tf32(o2.z * inv); w2.w = f2tf32(o2.w * inv);
        w3.x = f2tf32(o3.x * inv); w3.y = f2tf32(o3.y * inv); w3.z = f2tf32(o3.z * inv); w3.w = f2tf32(o3.w * inv);
        dst[0] = w0; dst[1] = w1; dst[2] = w2; dst[3] = w3;
    }
}

// ---------------- host launcher ----------------
extern "C" void kernel_launch(void* const* d_in, const int* in_sizes, int n_in,
                              void* d_out, int out_size) {
    const float* x      = (const float*)d_in[0];
    const float* accatt = (const float*)d_in[1];
    const float* q_w    = (const float*)d_in[2];
    const float* k_w    = (const float*)d_in[3];
    const float* v_w    = (const float*)d_in[4];
    const float* proj_w = (const float*)d_in[5];
    const float* proj_b = (const float*)d_in[6];
    float* out = (float*)d_out;

    int* sel; cudaGetSymbolAddress((void**)&sel, g_sel);
    float *xt, *wq, *wk, *wv, *wp, *xsel, *qsel, *lout, *kall, *vall;
    cudaGetSymbolAddress((void**)&xt, g_xt);
    cudaGetSymbolAddress((void**)&wq, g_wq); cudaGetSymbolAddress((void**)&wk, g_wk);
    cudaGetSymbolAddress((void**)&wv, g_wv); cudaGetSymbolAddress((void**)&wp, g_wp);
    cudaGetSymbolAddress((void**)&xsel, g_xsel);
    cudaGetSymbolAddress((void**)&qsel, g_qsel);
    cudaGetSymbolAddress((void**)&lout, g_lout);
    cudaGetSymbolAddress((void**)&kall, g_kall);
    cudaGetSymbolAddress((void**)&vall, g_vall);

    cudaFuncSetAttribute(gemm_kernel, cudaFuncAttributeMaxDynamicSharedMemorySize, GSMEM);
    cudaFuncSetAttribute(attn_kernel, cudaFuncAttributeMaxDynamicSharedMemorySize, ATTN_SMEM_BYTES);

    // 1: top-k
    topk_kernel<<<B_, 256>>>(accatt, sel);
    // 2-3: tf32 pre-round x and weights
    round_kernel<<<4096, 256>>>((const float4*)x, (uint4*)xt, M_ALL * D_ / 4);
    round_w4_kernel<<<2048, 256>>>((const float4*)q_w, (uint4*)wq, (const float4*)k_w, (uint4*)wk,
                                   (const float4*)v_w, (uint4*)wv, (const float4*)proj_w, (uint4*)wp);
    // 4: gather selected rows
    gather_kernel<<<M_SEL, 192>>>(xt, sel, xsel);
    // 5: Q projection for selected rows
    Seg sq = { wq, qsel, nullptr };
    gemm_kernel<<<dim3(6, 29), 256, GSMEM>>>(xsel, sq, sq, sq, M_SEL, 6, nullptr);
    // 6 (profiled by ncu -s 5 -c 1): fused K | V | proj GEMM over all rows
    Seg sk = { wk, kall, nullptr };
    Seg sv = { wv, vall, nullptr };
    Seg sp = { wp, out, proj_b };
    gemm_kernel<<<dim3(18, 289), 256, GSMEM>>>(xt, sk, sv, sp, M_ALL, 6, nullptr);
    // 7: attention -> lout (tf32-rounded fp32)
    attn_kernel<<<B_ * H_, 256, ATTN_SMEM_BYTES>>>(qsel, kall, vall, lout);
    // 8: correction: overwrite selected rows of out with lout @ proj^T + bias
    Seg sc = { wp, out, proj_b };
    gemm_kernel<<<dim3(6, 29), 256, GSMEM>>>(lout, sc, sc, sc, M_SEL, 6, sel);
}

// round 7
// speedup vs baseline: 3.0156x; 1.0598x over previous
#include <cuda_runtime.h>
#include <cuda_bf16.h>
#include <cstdint>
#include <math_constants.h>

// ---------------- problem constants ----------------
#define B_   64
#define N_   577
#define D_   768
#define H_   12
#define HD_  64
#define KK_  57
#define SELN 58
#define M_ALL (B_ * N_)    // 36928
#define M_SEL (B_ * SELN)  // 3712

// ---------------- scratch ----------------
__device__ int   g_sel[M_SEL];
__device__ float g_xt[(size_t)M_ALL * D_];       // tf32-rounded x
__device__ float g_wq[D_ * D_], g_wk[D_ * D_], g_wv[D_ * D_], g_wp[D_ * D_];
__device__ float g_xsel[(size_t)M_SEL * D_];
__device__ float g_qsel[(size_t)M_SEL * D_];
__device__ float g_lout[(size_t)M_SEL * D_];
__device__ float g_kall[(size_t)M_ALL * D_];
__device__ float g_vall[(size_t)M_ALL * D_];

// ---------------- helpers ----------------
__device__ __forceinline__ uint32_t smem_u32(const void* p) {
    uint32_t a;
    asm("{ .reg .u64 t; cvta.to.shared.u64 t, %1; cvt.u32.u64 %0, t; }" : "=r"(a) : "l"(p));
    return a;
}
__device__ __forceinline__ void cp16(uint32_t dst, const void* src, uint32_t sz) {
    asm volatile("cp.async.cg.shared.global [%0], [%1], 16, %2;" :: "r"(dst), "l"(src), "r"(sz) : "memory");
}
#define CP_COMMIT() asm volatile("cp.async.commit_group;" ::: "memory")
#define CP_WAIT0()  asm volatile("cp.async.wait_group 0;" ::: "memory")
#define CP_WAIT1()  asm volatile("cp.async.wait_group 1;" ::: "memory")

__device__ __forceinline__ uint32_t f2tf32(float f) {
    uint32_t u;
    asm("cvt.rna.tf32.f32 %0, %1;" : "=r"(u) : "f"(f));
    return u;
}
__device__ __forceinline__ void ldsm4(uint32_t* r, uint32_t addr) {
    asm volatile("ldmatrix.sync.aligned.m8n8.x4.shared.b16 {%0,%1,%2,%3}, [%4];"
        : "=r"(r[0]), "=r"(r[1]), "=r"(r[2]), "=r"(r[3]) : "r"(addr));
}
__device__ __forceinline__ void mma_tf32(float* d, const uint32_t* a, const uint32_t* b) {
    asm volatile(
        "mma.sync.aligned.m16n8k8.row.col.f32.tf32.tf32.f32 "
        "{%0,%1,%2,%3}, {%4,%5,%6,%7}, {%8,%9}, {%0,%1,%2,%3};"
        : "+f"(d[0]), "+f"(d[1]), "+f"(d[2]), "+f"(d[3])
        : "r"(a[0]), "r"(a[1]), "r"(a[2]), "r"(a[3]), "r"(b[0]), "r"(b[1]));
}

// ---------------- tf32 pre-round: dst = rna(src) ----------------
__global__ void round_kernel(const float4* __restrict__ src, uint4* __restrict__ dst, int n4) {
    int i = blockIdx.x * blockDim.x + threadIdx.x;
    int stride = gridDim.x * blockDim.x;
    for (; i < n4; i += stride) {
        float4 v = src[i];
        uint4 o;
        o.x = f2tf32(v.x); o.y = f2tf32(v.y); o.z = f2tf32(v.z); o.w = f2tf32(v.w);
        dst[i] = o;
    }
}
// 4 weights in one launch, segmented by blockIdx.x
__global__ void round_w4_kernel(const float4* w0, uint4* d0, const float4* w1, uint4* d1,
                                const float4* w2, uint4* d2, const float4* w3, uint4* d3) {
    int s = blockIdx.x >> 9;
    int local = blockIdx.x & 511;
    const float4* src = s == 0 ? w0 : s == 1 ? w1 : s == 2 ? w2 : w3;
    uint4* dst = s == 0 ? d0 : s == 1 ? d1 : s == 2 ? d2 : d3;
    const int n4 = D_ * D_ / 4;
    for (int i = local * 256 + threadIdx.x; i < n4; i += 512 * 256) {
        float4 v = src[i];
        uint4 o;
        o.x = f2tf32(v.x); o.y = f2tf32(v.y); o.z = f2tf32(v.z); o.w = f2tf32(v.w);
        dst[i] = o;
    }
}

// ---------------- top-k (iterative argmax, one block per batch) ----------------
__global__ void topk_kernel(const float* __restrict__ acc, int* __restrict__ sel) {
    int b = blockIdx.x;
    __shared__ float vals[N_ - 1];
    __shared__ float rv[256];
    __shared__ int   ri[256];
    int t = threadIdx.x;
    const float* src = acc + (size_t)b * N_ * N_ + 1;
    for (int i = t; i < N_ - 1; i += 256) vals[i] = src[i];
    if (t == 0) sel[b * SELN] = 0;
    __syncthreads();
    for (int it = 0; it < KK_; it++) {
        float best = -CUDART_INF_F; int bi = 0;
        for (int i = t; i < N_ - 1; i += 256) {
            float v = vals[i];
            if (v > best) { best = v; bi = i; }
        }
        rv[t] = best; ri[t] = bi;
        __syncthreads();
        for (int s = 128; s > 0; s >>= 1) {
            if (t < s && rv[t + s] > rv[t]) { rv[t] = rv[t + s]; ri[t] = ri[t + s]; }
            __syncthreads();
        }
        if (t == 0) { sel[b * SELN + 1 + it] = ri[0] + 1; vals[ri[0]] = -CUDART_INF_F; }
        __syncthreads();
    }
}

// ---------------- gather selected rows of xt ----------------
__global__ void gather_kernel(const float* __restrict__ x, const int* __restrict__ sel,
                              float* __restrict__ dst) {
    int m = blockIdx.x;
    int b = m / SELN;
    int tok = sel[m];
    const float4* s = (const float4*)(x + ((size_t)(b * N_ + tok)) * D_);
    float4* d = (float4*)(dst + (size_t)m * D_);
    int i = threadIdx.x;
    d[i] = s[i];
}

// ---------------- TF32 HMMA GEMM (inputs pre-rounded, ldmatrix fragments) -----
// Segmented along grid.x. C[m, col0+c] = sum_k A[m,k]*B[col0+c,k] (+bias).
// BM=128 BN=128 BK=32, 256 threads = 8 warps (2 m x 4 n), warp tile 64x32.
// smem tile: 128 rows x 36 floats (32 data + 4 pad) per operand.
// If selmap != null, output row m remaps to (m/SELN)*N_ + selmap[m].
struct Seg {
    const float* bw;
    float* c;
    const float* bias;
};
#define TSTRIDE 36
#define TILE_B  (128 * TSTRIDE * 4)     // 18432
#define STG     (2 * TILE_B)            // 36864
#define GSMEM   (2 * STG)               // 73728
#define KITERS  (D_ / 32)               // 24

__global__ __launch_bounds__(256, 2) void gemm_kernel(
    const float* __restrict__ A,
    Seg s0, Seg s1, Seg s2,
    int M, int per, const int* __restrict__ selmap)
{
    extern __shared__ char smem[];
    uint32_t sb = smem_u32(smem);
    int tid = threadIdx.x;
    int lane = tid & 31;
    int wid = tid >> 5;
    int wm = wid & 1, wn = wid >> 1;
    int gid = lane >> 2, tig = lane & 3;
    int bx = blockIdx.x, by = blockIdx.y;

    int seg = bx / per;
    Seg S = (seg == 0) ? s0 : (seg == 1) ? s1 : s2;
    int nb = bx - seg * per;
    const float* Bw = S.bw;
    float* C = S.c;
    const float* bias = S.bias;
    int col0 = nb * 128;
    int row0 = by * 128;

    float acc[4][4][4];
#pragma unroll
    for (int i = 0; i < 4; i++)
#pragma unroll
        for (int j = 0; j < 4; j++)
#pragma unroll
            for (int r = 0; r < 4; r++) acc[i][j][r] = 0.f;

    // ldmatrix per-lane address components (byte offsets within a tile)
    // A (x4): matrices (rows g0..g0+7, k c..c+3), (rows +8, same), (rows, c+4..7), (rows+8, c+4..7)
    uint32_t a_lrow = (uint32_t)(wm * 64 + (lane & 15));
    uint32_t a_lcol = (uint32_t)((lane >> 4) * 4);
    uint32_t a_base_off = (a_lrow * TSTRIDE + a_lcol) * 4;
    // B (x4 per pair p): rows wn*32+p*16+((lane>>4)&1)*8+(lane&7), col ((lane>>3)&1)*4
    uint32_t b_lrow = (uint32_t)(wn * 32 + (((lane >> 4) & 1) * 8) + (lane & 7));
    uint32_t b_lcol = (uint32_t)(((lane >> 3) & 1) * 4);
    uint32_t b_base_off = (b_lrow * TSTRIDE + b_lcol) * 4;

    auto load_stage = [&](int buf, int k0) {
        uint32_t base = sb + buf * STG;
#pragma unroll
        for (int q = 0; q < 4; q++) {
            int idx = tid + q * 256;            // 0..1023
            int r = idx >> 3, c8 = idx & 7;     // row, 16B chunk
            int gm = row0 + r;
            uint32_t sz = (gm < M) ? 16u : 0u;
            int cg = gm < M ? gm : (M - 1);
            cp16(base + r * 144 + c8 * 16, A + (size_t)cg * D_ + k0 + c8 * 4, sz);
            cp16(base + TILE_B + r * 144 + c8 * 16,
                 Bw + (size_t)(col0 + r) * D_ + k0 + c8 * 4, 16u);
        }
    };

    load_stage(0, 0);
    CP_COMMIT();

    for (int it = 0; it < KITERS; it++) {
        int buf = it & 1;
        if (it + 1 < KITERS) {
            load_stage(buf ^ 1, (it + 1) * 32);
            CP_COMMIT();
            CP_WAIT1();
        } else {
            CP_WAIT0();
        }
        __syncthreads();

        uint32_t As_u = sb + buf * STG;
        uint32_t Bs_u = As_u + TILE_B;
        uint32_t a_addr = As_u + a_base_off;
        uint32_t b_addr = Bs_u + b_base_off;

#pragma unroll
        for (int ks = 0; ks < 4; ks++) {
            uint32_t kb = (uint32_t)(ks * 32);  // k offset in bytes
            uint32_t af[4][4], bf[4][2];
#pragma unroll
            for (int i = 0; i < 4; i++)
                ldsm4(af[i], a_addr + kb + (uint32_t)(i * 16 * TSTRIDE * 4));
#pragma unroll
            for (int p = 0; p < 2; p++) {
                uint32_t tmp[4];
                ldsm4(tmp, b_addr + kb + (uint32_t)(p * 16 * TSTRIDE * 4));
                bf[p * 2 + 0][0] = tmp[0]; bf[p * 2 + 0][1] = tmp[1];
                bf[p * 2 + 1][0] = tmp[2]; bf[p * 2 + 1][1] = tmp[3];
            }
#pragma unroll
            for (int i = 0; i < 4; i++)
#pragma unroll
                for (int j = 0; j < 4; j++)
                    mma_tf32(acc[i][j], af[i], bf[j]);
        }
        __syncthreads();
    }

    // epilogue (optional row remap through selmap)
#pragma unroll
    for (int i = 0; i < 4; i++) {
        int r0 = row0 + wm * 64 + i * 16 + gid;
        int r1 = r0 + 8;
        size_t g0 = 0, g1 = 0;
        bool v0 = r0 < M, v1 = r1 < M;
        if (selmap) {
            if (v0) g0 = (size_t)((r0 / SELN) * N_ + selmap[r0]) * D_;
            if (v1) g1 = (size_t)((r1 / SELN) * N_ + selmap[r1]) * D_;
        } else {
            g0 = (size_t)r0 * D_;
            g1 = (size_t)r1 * D_;
        }
#pragma unroll
        for (int j = 0; j < 4; j++) {
            int col = col0 + wn * 32 + j * 8 + tig * 2;
            float b0 = 0.f, b1 = 0.f;
            if (bias) { b0 = bias[col]; b1 = bias[col + 1]; }
            if (v0) {
                float2 o; o.x = acc[i][j][0] + b0; o.y = acc[i][j][1] + b1;
                *(float2*)(C + g0 + col) = o;
            }
            if (v1) {
                float2 o; o.x = acc[i][j][2] + b0; o.y = acc[i][j][3] + b1;
                *(float2*)(C + g1 + col) = o;
            }
        }
    }
}

// ---------------- attention: one block per (b, h), 58 queries ----------------
#define ATTN_SMEM_FLOATS (N_ * 64 + 64 * 64 + 64 + 64 + 256)
#define ATTN_SMEM_BYTES  (ATTN_SMEM_FLOATS * 4)

__global__ __launch_bounds__(256) void attn_kernel(
    const float* __restrict__ qsel, const float* __restrict__ kall,
    const float* __restrict__ vall, float* __restrict__ lout)
{
    extern __shared__ float sm[];
    float* P    = sm;                   // [577][64]
    float* Ks   = P + N_ * 64;          // [64][64]
    float* mx   = Ks + 64 * 64;         // [64]
    float* sums = mx + 64;              // [64]
    float* red  = sums + 64;            // [4][64]

    int bh = blockIdx.x;
    int h = bh % H_;
    int b = bh / H_;
    int t = threadIdx.x;
    int j = t & 63;
    int g = t >> 6;

    float4 q4[16];
    if (j < SELN) {
        const float4* qr = (const float4*)(qsel + ((size_t)(b * SELN + j)) * D_ + h * HD_);
#pragma unroll
        for (int i = 0; i < 16; i++) q4[i] = qr[i];
    } else {
#pragma unroll
        for (int i = 0; i < 16; i++) q4[i] = make_float4(0.f, 0.f, 0.f, 0.f);
    }

    // scores
    for (int n0 = 0; n0 < N_; n0 += 64) {
        int nend = min(64, N_ - n0);
        __syncthreads();
        for (int idx = t; idx < nend * 16; idx += 256) {
            int r = idx >> 4, cc = idx & 15;
            ((float4*)Ks)[r * 16 + cc] =
                *(const float4*)(kall + ((size_t)(b * N_ + n0 + r)) * D_ + h * HD_ + cc * 4);
        }
        __syncthreads();
#pragma unroll
        for (int i = 0; i < 16; i++) {
            int n = g * 16 + i;
            if (n < nend) {
                const float4* kr = (const float4*)(Ks + n * 64);
                float s = 0.f;
#pragma unroll
                for (int d = 0; d < 16; d++) {
                    float4 k = kr[d];
                    s += q4[d].x * k.x + q4[d].y * k.y + q4[d].z * k.z + q4[d].w * k.w;
                }
                P[(n0 + n) * 64 + j] = s * 0.125f;
            }
        }
    }
    __syncthreads();

    // softmax over keys per query j
    float m = -CUDART_INF_F;
    for (int n = g; n < N_; n += 4) m = fmaxf(m, P[n * 64 + j]);
    red[g * 64 + j] = m;
    __syncthreads();
    if (g == 0) mx[j] = fmaxf(fmaxf(red[j], red[64 + j]), fmaxf(red[128 + j], red[192 + j]));
    __syncthreads();
    float mm = mx[j];
    float ssum = 0.f;
    for (int n = g; n < N_; n += 4) {
        float e = __expf(P[n * 64 + j] - mm);
        P[n * 64 + j] = e;
        ssum += e;
    }
    red[g * 64 + j] = ssum;
    __syncthreads();
    if (g == 0) sums[j] = red[j] + red[64 + j] + red[128 + j] + red[192 + j];
    __syncthreads();
    float inv = 1.f / sums[j];

    // O = P @ V
    float4 o0 = make_float4(0.f, 0.f, 0.f, 0.f), o1 = o0, o2 = o0, o3 = o0;
    for (int n0 = 0; n0 < N_; n0 += 64) {
        int nend = min(64, N_ - n0);
        __syncthreads();
        for (int idx = t; idx < nend * 16; idx += 256) {
            int r = idx >> 4, cc = idx & 15;
            ((float4*)Ks)[r * 16 + cc] =
                *(const float4*)(vall + ((size_t)(b * N_ + n0 + r)) * D_ + h * HD_ + cc * 4);
        }
        __syncthreads();
        for (int n = 0; n < nend; n++) {
            float p = P[(n0 + n) * 64 + j];
            const float4* vr = (const float4*)(Ks + n * 64 + g * 16);
            float4 v0 = vr[0], v1 = vr[1], v2 = vr[2], v3 = vr[3];
            o0.x += p * v0.x; o0.y += p * v0.y; o0.z += p * v0.z; o0.w += p * v0.w;
            o1.x += p * v1.x; o1.y += p * v1.y; o1.z += p * v1.z; o1.w += p * v1.w;
            o2.x += p * v2.x; o2.y += p * v2.y; o2.z += p * v2.z; o2.w += p * v2.w;
            o3.x += p * v3.x; o3.y += p * v3.y; o3.z += p * v3.z; o3.w += p * v3.w;
        }
    }

    if (j < SELN) {
        // tf32-round the attention output so the correction GEMM needs no cvt
        uint4* dst = (uint4*)(lout + ((size_t)(b * SELN + j)) * D_ + h * HD_ + g * 16);
        uint4 w0, w1, w2, w3;
        w0.x = f2tf32(o0.x * inv); w0.y = f2tf32(o0.y * inv); w0.z = f2tf32(o0.z * inv); w0.w = f2tf32(o0.w * inv);
        w1.x = f2tf32(o1.x * inv); w1.y = f2tf32(o1.y * inv); w1.z = f2tf32(o1.z * inv); w1.w = f2tf32(o1.w * inv);
        w2.x = f2tf32(o2.x * inv); w2.y = f2tf32(o2.y * inv); w2.z = f2tf32(o2.z * inv); w2.w = f2tf32(o2.w * inv);
        w3.x = f2tf32(o3.x * inv); w3.y = f2tf32(o3.y * inv); w3.z = f2tf32(o3.z * inv); w3.w = f2tf32(o3.w * inv);
        dst[0] = w0; dst[1] = w1; dst[2] = w2; dst[3] = w3;
    }
}

// ---------------- host launcher ----------------
extern "C" void kernel_launch(void* const* d_in, const int* in_sizes, int n_in,
                              void* d_out, int out_size) {
    const float* x      = (const float*)d_in[0];
    const float* accatt = (const float*)d_in[1];
    const float* q_w    = (const float*)d_in[2];
    const float* k_w    = (const float*)d_in[3];
    const float* v_w    = (const float*)d_in[4];
    const float* proj_w = (const float*)d_in[5];
    const float* proj_b = (const float*)d_in[6];
    float* out = (float*)d_out;

    int* sel; cudaGetSymbolAddress((void**)&sel, g_sel);
    float *xt, *wq, *wk, *wv, *wp, *xsel, *qsel, *lout, *kall, *vall;
    cudaGetSymbolAddress((void**)&xt, g_xt);
    cudaGetSymbolAddress((void**)&wq, g_wq); cudaGetSymbolAddress((void**)&wk, g_wk);
    cudaGetSymbolAddress((void**)&wv, g_wv); cudaGetSymbolAddress((void**)&wp, g_wp);
    cudaGetSymbolAddress((void**)&xsel, g_xsel);
    cudaGetSymbolAddress((void**)&qsel, g_qsel);
    cudaGetSymbolAddress((void**)&lout, g_lout);
    cudaGetSymbolAddress((void**)&kall, g_kall);
    cudaGetSymbolAddress((void**)&vall, g_vall);

    cudaFuncSetAttribute(gemm_kernel, cudaFuncAttributeMaxDynamicSharedMemorySize, GSMEM);
    cudaFuncSetAttribute(attn_kernel, cudaFuncAttributeMaxDynamicSharedMemorySize, ATTN_SMEM_BYTES);

    // 1: top-k
    topk_kernel<<<B_, 256>>>(accatt, sel);
    // 2-3: tf32 pre-round x and weights
    round_kernel<<<4096, 256>>>((const float4*)x, (uint4*)xt, M_ALL * D_ / 4);
    round_w4_kernel<<<2048, 256>>>((const float4*)q_w, (uint4*)wq, (const float4*)k_w, (uint4*)wk,
                                   (const float4*)v_w, (uint4*)wv, (const float4*)proj_w, (uint4*)wp);
    // 4: gather selected rows
    gather_kernel<<<M_SEL, 192>>>(xt, sel, xsel);
    // 5: Q projection for selected rows
    Seg sq = { wq, qsel, nullptr };
    gemm_kernel<<<dim3(6, 29), 256, GSMEM>>>(xsel, sq, sq, sq, M_SEL, 6, nullptr);
    // 6: fused K | V | proj GEMM over all rows
    Seg sk = { wk, kall, nullptr };
    Seg sv = { wv, vall, nullptr };
    Seg sp = { wp, out, proj_b };
    gemm_kernel<<<dim3(18, 289), 256, GSMEM>>>(xt, sk, sv, sp, M_ALL, 6, nullptr);
    // 7: attention -> lout (tf32-rounded fp32)
    attn_kernel<<<B_ * H_, 256, ATTN_SMEM_BYTES>>>(qsel, kall, vall, lout);
    // 8: correction: overwrite selected rows of out with lout @ proj^T + bias
    Seg sc = { wp, out, proj_b };
    gemm_kernel<<<dim3(6, 29), 256, GSMEM>>>(lout, sc, sc, sc, M_SEL, 6, sel);
}